// round 8
// baseline (speedup 1.0000x reference)
#include <cuda_runtime.h>
#include <cuda_bf16.h>
#include <cstdint>
#include <cstddef>

#define CKDIM 64
#define K2    128
#define NP    4096
#define NN    8192
#define NV    1024
#define NBLK  64

// ---------------- scratch ----------------
__device__ float g_ST[(size_t)NP * NN];            // E^T[p][n], tf32-rounded (134 MB)
__device__ __nv_bfloat16 g_Qh[(size_t)NP * K2];
__device__ __nv_bfloat16 g_Ql[(size_t)NP * K2];
__device__ __nv_bfloat16 g_Mh[(size_t)NN * K2];
__device__ __nv_bfloat16 g_Ml[(size_t)NN * K2];
__device__ float g_MV[(size_t)NV * NN];            // tf32-rounded mv (K-major)
__device__ float g_bsq[NP];
__device__ float g_msn[NN];
__device__ float g_part[(size_t)NBLK * NP];
__device__ float g_rinv[NP];

__device__ __forceinline__ float tf32r(float x) {
    uint32_t u;
    asm("cvt.rna.tf32.f32 %0, %1;" : "=r"(u) : "f"(x));
    return __uint_as_float(u);
}
__device__ __forceinline__ void cp16(uint32_t dst, const void* src) {
    asm volatile("cp.async.cg.shared.global [%0], [%1], 16;\n" :: "r"(dst), "l"(src));
}
__device__ __forceinline__ uint32_t smem_u32(const void* p) {
    return (uint32_t)__cvta_generic_to_shared(p);
}
#define MMA_BF16(acc, a, b)                                                          \
    asm volatile(                                                                    \
        "mma.sync.aligned.m16n8k16.row.col.f32.bf16.bf16.f32 "                       \
        "{%0,%1,%2,%3}, {%4,%5,%6,%7}, {%8,%9}, {%0,%1,%2,%3};\n"                    \
        : "+f"((acc)[0]), "+f"((acc)[1]), "+f"((acc)[2]), "+f"((acc)[3])             \
        : "r"((a)[0]), "r"((a)[1]), "r"((a)[2]), "r"((a)[3]),                        \
          "r"((b)[0]), "r"((b)[1]))
#define MMA_TF32(acc, a, b)                                                          \
    asm volatile(                                                                    \
        "mma.sync.aligned.m16n8k8.row.col.f32.tf32.tf32.f32 "                        \
        "{%0,%1,%2,%3}, {%4,%5,%6,%7}, {%8,%9}, {%0,%1,%2,%3};\n"                    \
        : "+f"((acc)[0]), "+f"((acc)[1]), "+f"((acc)[2]), "+f"((acc)[3])             \
        : "r"(__float_as_uint((a)[0])), "r"(__float_as_uint((a)[1])),                \
          "r"(__float_as_uint((a)[2])), "r"(__float_as_uint((a)[3])),                \
          "r"(__float_as_uint((b)[0])), "r"(__float_as_uint((b)[1])))

// ---------------- prep kernels ----------------
__global__ void prep_q_kernel(const float* __restrict__ qk, const float* __restrict__ qe) {
    int p = blockIdx.x * blockDim.x + threadIdx.x;
    if (p >= NP) return;
    float bsq = 0.f;
#pragma unroll
    for (int c = 0; c < CKDIM; ++c) {
        float k = qk[c * NP + p];
        float e = qe[c * NP + p];
        float b1 = 2.f * k * e;
        float b2 = -e;
        __nv_bfloat16 h1 = __float2bfloat16(b1);
        __nv_bfloat16 h2 = __float2bfloat16(b2);
        g_Qh[(size_t)p * K2 + c]         = h1;
        g_Ql[(size_t)p * K2 + c]         = __float2bfloat16(b1 - __bfloat162float(h1));
        g_Qh[(size_t)p * K2 + CKDIM + c] = h2;
        g_Ql[(size_t)p * K2 + CKDIM + c] = __float2bfloat16(b2 - __bfloat162float(h2));
        bsq = fmaf(e * k, k, bsq);
    }
    g_bsq[p] = bsq;
}

__global__ void prep_m_kernel(const float* __restrict__ mk, const float* __restrict__ ms) {
    int n = blockIdx.x * blockDim.x + threadIdx.x;
    if (n >= NN) return;
#pragma unroll
    for (int c = 0; c < CKDIM; ++c) {
        float v = mk[c * NN + n];
        float v2 = v * v;
        __nv_bfloat16 h = __float2bfloat16(v);
        __nv_bfloat16 h2 = __float2bfloat16(v2);
        g_Mh[(size_t)n * K2 + c]         = h;
        g_Ml[(size_t)n * K2 + c]         = __float2bfloat16(v - __bfloat162float(h));
        g_Mh[(size_t)n * K2 + CKDIM + c] = h2;
        g_Ml[(size_t)n * K2 + CKDIM + c] = __float2bfloat16(v2 - __bfloat162float(h2));
    }
    g_msn[n] = ms[n] * 0.125f;
}

__global__ void prep_mv_kernel(const float* __restrict__ mv) {
    size_t i = (size_t)blockIdx.x * blockDim.x + threadIdx.x;
    float4 v = ((const float4*)mv)[i];
    v.x = tf32r(v.x); v.y = tf32r(v.y); v.z = tf32r(v.z); v.w = tf32r(v.w);
    ((float4*)g_MV)[i] = v;
}

// ---------------- sim kernel: split-bf16 m16n8k16, writes E^T + row partials ------
#define STILE 5120
#define SWORDS 2560

__global__ __launch_bounds__(256, 2) void sim_kernel() {
    extern __shared__ __nv_bfloat16 sm16[];
    const uint32_t* w32 = (const uint32_t*)sm16;
    __shared__ float red[2][128];

    const int tid  = threadIdx.x;
    const int bNn  = blockIdx.x * 128;
    const int bNp  = blockIdx.y * 128;
    const int warp = tid >> 5;
    const int lane = tid & 31;
    const int wm = (warp & 3) * 32;
    const int nw = warp >> 2;
    const int wn = nw * 64;
    const int g  = lane >> 2;
    const int tg = lane & 3;

    float acc[2][8][4];
#pragma unroll
    for (int i = 0; i < 2; ++i)
#pragma unroll
        for (int j = 0; j < 8; ++j)
#pragma unroll
            for (int r = 0; r < 4; ++r) acc[i][j][r] = 0.f;

    const __nv_bfloat16* gsrc[4] = {g_Qh, g_Ql, g_Mh, g_Ml};
    auto load_tiles = [&](int kt, int st) {
#pragma unroll
        for (int t = 0; t < 4; ++t) {
            int rowbase = (t < 2) ? bNp : bNn;
#pragma unroll
            for (int s = 0; s < 2; ++s) {
                int id = tid + s * 256;
                int r  = id >> 2;
                int c  = id & 3;
                uint32_t dst = smem_u32(sm16) +
                               ((t * 2 + st) * STILE + r * 40 + c * 8) * 2;
                cp16(dst, &gsrc[t][(size_t)(rowbase + r) * K2 + kt * 32 + c * 8]);
            }
        }
        asm volatile("cp.async.commit_group;\n" ::);
    };

    load_tiles(0, 0);

    for (int kt = 0; kt < 4; ++kt) {
        const int cur = kt & 1;
        if (kt + 1 < 4) {
            load_tiles(kt + 1, cur ^ 1);
            asm volatile("cp.async.wait_group 1;\n" ::);
        } else {
            asm volatile("cp.async.wait_group 0;\n" ::);
        }
        __syncthreads();

        const int qh = (0 * 2 + cur) * SWORDS;
        const int ql = (1 * 2 + cur) * SWORDS;
        const int mh = (2 * 2 + cur) * SWORDS;
        const int ml = (3 * 2 + cur) * SWORDS;

#pragma unroll
        for (int ks = 0; ks < 2; ++ks) {
            const int k0 = ks * 8;
            uint32_t ah[2][4], al[2][4], bh[8][2], bl[8][2];
#pragma unroll
            for (int i = 0; i < 2; ++i) {
                int r0 = (wm + 16 * i + g) * 20 + k0;
                int r8 = r0 + 8 * 20;
                ah[i][0] = w32[qh + r0 + tg];     ah[i][1] = w32[qh + r8 + tg];
                ah[i][2] = w32[qh + r0 + tg + 4]; ah[i][3] = w32[qh + r8 + tg + 4];
                al[i][0] = w32[ql + r0 + tg];     al[i][1] = w32[ql + r8 + tg];
                al[i][2] = w32[ql + r0 + tg + 4]; al[i][3] = w32[ql + r8 + tg + 4];
            }
#pragma unroll
            for (int j = 0; j < 8; ++j) {
                int nr = (wn + 8 * j + g) * 20 + k0;
                bh[j][0] = w32[mh + nr + tg]; bh[j][1] = w32[mh + nr + tg + 4];
                bl[j][0] = w32[ml + nr + tg]; bl[j][1] = w32[ml + nr + tg + 4];
            }
#pragma unroll
            for (int i = 0; i < 2; ++i)
#pragma unroll
                for (int j = 0; j < 8; ++j) {
                    MMA_BF16(acc[i][j], ah[i], bh[j]);
                    MMA_BF16(acc[i][j], al[i], bh[j]);
                    MMA_BF16(acc[i][j], ah[i], bl[j]);
                }
        }
        __syncthreads();
    }

    float bsqr[2][2];
#pragma unroll
    for (int i = 0; i < 2; ++i) {
        int r0 = bNp + wm + 16 * i + g;
        bsqr[i][0] = g_bsq[r0];
        bsqr[i][1] = g_bsq[r0 + 8];
    }
    float msv[8][2];
#pragma unroll
    for (int j = 0; j < 8; ++j) {
        int c0 = bNn + wn + 8 * j + 2 * tg;
        msv[j][0] = g_msn[c0];
        msv[j][1] = g_msn[c0 + 1];
    }
    float rsum[2][2];
    rsum[0][0] = rsum[0][1] = rsum[1][0] = rsum[1][1] = 0.f;

#pragma unroll
    for (int i = 0; i < 2; ++i) {
        int r0 = bNp + wm + 16 * i + g;
        int r1 = r0 + 8;
#pragma unroll
        for (int j = 0; j < 8; ++j) {
            int c0 = bNn + wn + 8 * j + 2 * tg;
            float e0 = tf32r(__expf(msv[j][0] * (acc[i][j][0] - bsqr[i][0])));
            float e1 = tf32r(__expf(msv[j][1] * (acc[i][j][1] - bsqr[i][0])));
            float e2 = tf32r(__expf(msv[j][0] * (acc[i][j][2] - bsqr[i][1])));
            float e3 = tf32r(__expf(msv[j][1] * (acc[i][j][3] - bsqr[i][1])));
            *(float2*)&g_ST[(size_t)r0 * NN + c0] = make_float2(e0, e1);
            *(float2*)&g_ST[(size_t)r1 * NN + c0] = make_float2(e2, e3);
            rsum[i][0] += e0 + e1;
            rsum[i][1] += e2 + e3;
        }
    }
#pragma unroll
    for (int i = 0; i < 2; ++i)
#pragma unroll
        for (int d = 0; d < 2; ++d) {
            float s = rsum[i][d];
            s += __shfl_xor_sync(0xffffffffu, s, 1);
            s += __shfl_xor_sync(0xffffffffu, s, 2);
            if (tg == 0) red[nw][wm + 16 * i + 8 * d + g] = s;
        }
    __syncthreads();
    if (tid < 128)
        g_part[(size_t)blockIdx.x * NP + bNp + tid] = red[0][tid] + red[1][tid];
}

// ---------------- rinv ----------------
__global__ void rinv_kernel() {
    int p = blockIdx.x * blockDim.x + threadIdx.x;
    float s = 0.f;
#pragma unroll
    for (int b = 0; b < NBLK; ++b) s += g_part[(size_t)b * NP + p];
    g_rinv[p] = 1.0f / s;
}

// ---------------- readout GEMM: tf32 mma.sync, CTA 128x128, 2 CTAs/SM -----------
// out[v][p] = rinv[p] * sum_n MV[v][n] * E^T[p][n]
#define OBK   32
#define ONKT  (NN / OBK)        // 256
#define OAW   36                // row stride in fp32 words (144 B)
#define OTSZ  (128 * OAW * 4)   // 18432 B per operand tile
#define OSTG  (2 * OTSZ)        // 36864 B per stage
#define OSMEM (3 * OSTG)        // 110592 B

__global__ __launch_bounds__(256, 2) void out_gemm_kernel(float* __restrict__ out) {
    extern __shared__ float Sf[];
    const int tid  = threadIdx.x;
    const int warp = tid >> 5;
    const int lane = tid & 31;
    const int bM = blockIdx.x * 128;   // v offset (x fastest -> 8 CTAs share B strip)
    const int bN = blockIdx.y * 128;   // p offset
    const int wm = (warp & 3) * 32;    // v warp tile (32)
    const int wn = (warp >> 2) * 64;   // p warp tile (64)
    const int g  = lane >> 2;
    const int tg = lane & 3;
    const uint32_t sbase = smem_u32(Sf);

    float acc[2][8][4];
#pragma unroll
    for (int i = 0; i < 2; ++i)
#pragma unroll
        for (int j = 0; j < 8; ++j)
#pragma unroll
            for (int r = 0; r < 4; ++r) acc[i][j][r] = 0.f;

    auto load_stage = [&](int kt, int st) {
        uint32_t ab = sbase + st * OSTG;
        uint32_t bb = ab + OTSZ;
#pragma unroll
        for (int s = 0; s < 4; ++s) {          // A: 1024 16B chunks
            int id = tid + s * 256;
            int r = id >> 3, c = id & 7;
            cp16(ab + r * 144 + c * 16, &g_MV[(size_t)(bM + r) * NN + kt * OBK + c * 4]);
        }
#pragma unroll
        for (int s = 0; s < 4; ++s) {          // B: 1024 16B chunks
            int id = tid + s * 256;
            int r = id >> 3, c = id & 7;
            cp16(bb + r * 144 + c * 16, &g_ST[(size_t)(bN + r) * NN + kt * OBK + c * 4]);
        }
        asm volatile("cp.async.commit_group;\n" ::);
    };

    load_stage(0, 0);
    load_stage(1, 1);
    load_stage(2, 2);

    for (int kt = 0; kt < ONKT; ++kt) {
        if (kt < ONKT - 2)       asm volatile("cp.async.wait_group 2;\n" ::);
        else if (kt == ONKT - 2) asm volatile("cp.async.wait_group 1;\n" ::);
        else                     asm volatile("cp.async.wait_group 0;\n" ::);
        __syncthreads();

        const int abase = (kt % 3) * (OSTG / 4);
        const int bbase = abase + OTSZ / 4;

#pragma unroll
        for (int ks = 0; ks < 4; ++ks) {
            const int k0 = ks * 8;
            float af[2][4];
#pragma unroll
            for (int i = 0; i < 2; ++i) {
                int r0 = abase + (wm + 16 * i + g) * OAW + k0;
                int r8 = r0 + 8 * OAW;
                af[i][0] = Sf[r0 + tg];     af[i][1] = Sf[r8 + tg];
                af[i][2] = Sf[r0 + tg + 4]; af[i][3] = Sf[r8 + tg + 4];
            }
            float bf[8][2];
#pragma unroll
            for (int j = 0; j < 8; ++j) {
                int nr = bbase + (wn + 8 * j + g) * OAW + k0;
                bf[j][0] = Sf[nr + tg];
                bf[j][1] = Sf[nr + tg + 4];
            }
#pragma unroll
            for (int i = 0; i < 2; ++i)
#pragma unroll
                for (int j = 0; j < 8; ++j)
                    MMA_TF32(acc[i][j], af[i], bf[j]);
        }
        __syncthreads();
        if (kt + 3 < ONKT) load_stage(kt + 3, (kt + 3) % 3);
    }

    // epilogue: scale by rinv[p]
#pragma unroll
    for (int j = 0; j < 8; ++j) {
        int c = bN + wn + 8 * j + 2 * tg;
        float r0 = g_rinv[c];
        float r1 = g_rinv[c + 1];
#pragma unroll
        for (int i = 0; i < 2; ++i) {
            int rr = bM + wm + 16 * i + g;
            *(float2*)&out[(size_t)rr * NP + c] =
                make_float2(acc[i][j][0] * r0, acc[i][j][1] * r1);
            *(float2*)&out[(size_t)(rr + 8) * NP + c] =
                make_float2(acc[i][j][2] * r0, acc[i][j][3] * r1);
        }
    }
}

// ---------------- launch ----------------
extern "C" void kernel_launch(void* const* d_in, const int* in_sizes, int n_in,
                              void* d_out, int out_size) {
    const float* qk = (const float*)d_in[0];
    const float* qe = (const float*)d_in[1];
    const float* mk = (const float*)d_in[2];
    const float* ms = (const float*)d_in[3];
    const float* mv = (const float*)d_in[4];
    float* out = (float*)d_out;

    const int SIM_SMEM = 8 * STILE * 2;   // 81920 B
    cudaFuncSetAttribute(sim_kernel, cudaFuncAttributeMaxDynamicSharedMemorySize, SIM_SMEM);
    cudaFuncSetAttribute(out_gemm_kernel, cudaFuncAttributeMaxDynamicSharedMemorySize, OSMEM);

    prep_q_kernel<<<NP / 256, 256>>>(qk, qe);
    prep_m_kernel<<<NN / 256, 256>>>(mk, ms);
    prep_mv_kernel<<<(NV * NN / 4) / 256, 256>>>(mv);
    sim_kernel<<<dim3(NN / 128, NP / 128), 256, SIM_SMEM>>>();
    rinv_kernel<<<NP / 256, 256>>>();
    out_gemm_kernel<<<dim3(NV / 128, NP / 128), 256, OSMEM>>>(out);
}

// round 9
// speedup vs baseline: 1.0524x; 1.0524x over previous
#include <cuda_runtime.h>
#include <cuda_bf16.h>
#include <cstdint>
#include <cstddef>

#define CKDIM 64
#define K2    128
#define NP    4096
#define NN    8192
#define NV    1024
#define NBLK  64

// ---------------- scratch ----------------
__device__ float g_ST[(size_t)NP * NN];            // E^T[p][n], tf32-rounded (134 MB)
__device__ __nv_bfloat16 g_Qh[(size_t)NP * K2];
__device__ __nv_bfloat16 g_Ql[(size_t)NP * K2];
__device__ __nv_bfloat16 g_Mh[(size_t)NN * K2];
__device__ __nv_bfloat16 g_Ml[(size_t)NN * K2];
__device__ float g_MV[(size_t)NV * NN];            // tf32-rounded mv (K-major)
__device__ float g_bsq[NP];
__device__ float g_msn[NN];
__device__ float g_part[(size_t)NBLK * NP];
__device__ float g_rinv[NP];

__device__ __forceinline__ float tf32r(float x) {
    uint32_t u;
    asm("cvt.rna.tf32.f32 %0, %1;" : "=r"(u) : "f"(x));
    return __uint_as_float(u);
}
__device__ __forceinline__ void cp16(uint32_t dst, const void* src) {
    asm volatile("cp.async.cg.shared.global [%0], [%1], 16;\n" :: "r"(dst), "l"(src));
}
__device__ __forceinline__ uint32_t smem_u32(const void* p) {
    return (uint32_t)__cvta_generic_to_shared(p);
}
__device__ __forceinline__ void ldsm4(uint32_t* r, uint32_t addr) {
    asm volatile("ldmatrix.sync.aligned.m8n8.x4.shared.b16 {%0,%1,%2,%3}, [%4];"
                 : "=r"(r[0]), "=r"(r[1]), "=r"(r[2]), "=r"(r[3]) : "r"(addr));
}
#define MMA_BF16(acc, a, b)                                                          \
    asm volatile(                                                                    \
        "mma.sync.aligned.m16n8k16.row.col.f32.bf16.bf16.f32 "                       \
        "{%0,%1,%2,%3}, {%4,%5,%6,%7}, {%8,%9}, {%0,%1,%2,%3};\n"                    \
        : "+f"((acc)[0]), "+f"((acc)[1]), "+f"((acc)[2]), "+f"((acc)[3])             \
        : "r"((a)[0]), "r"((a)[1]), "r"((a)[2]), "r"((a)[3]),                        \
          "r"((b)[0]), "r"((b)[1]))
#define MMA_TF32U(acc, a, b0, b1)                                                    \
    asm volatile(                                                                    \
        "mma.sync.aligned.m16n8k8.row.col.f32.tf32.tf32.f32 "                        \
        "{%0,%1,%2,%3}, {%4,%5,%6,%7}, {%8,%9}, {%0,%1,%2,%3};\n"                    \
        : "+f"((acc)[0]), "+f"((acc)[1]), "+f"((acc)[2]), "+f"((acc)[3])             \
        : "r"((a)[0]), "r"((a)[1]), "r"((a)[2]), "r"((a)[3]),                        \
          "r"(b0), "r"(b1))

// ---------------- prep kernels ----------------
__global__ void prep_q_kernel(const float* __restrict__ qk, const float* __restrict__ qe) {
    int p = blockIdx.x * blockDim.x + threadIdx.x;
    if (p >= NP) return;
    float bsq = 0.f;
#pragma unroll
    for (int c = 0; c < CKDIM; ++c) {
        float k = qk[c * NP + p];
        float e = qe[c * NP + p];
        float b1 = 2.f * k * e;
        float b2 = -e;
        __nv_bfloat16 h1 = __float2bfloat16(b1);
        __nv_bfloat16 h2 = __float2bfloat16(b2);
        g_Qh[(size_t)p * K2 + c]         = h1;
        g_Ql[(size_t)p * K2 + c]         = __float2bfloat16(b1 - __bfloat162float(h1));
        g_Qh[(size_t)p * K2 + CKDIM + c] = h2;
        g_Ql[(size_t)p * K2 + CKDIM + c] = __float2bfloat16(b2 - __bfloat162float(h2));
        bsq = fmaf(e * k, k, bsq);
    }
    g_bsq[p] = bsq;
}

__global__ void prep_m_kernel(const float* __restrict__ mk, const float* __restrict__ ms) {
    int n = blockIdx.x * blockDim.x + threadIdx.x;
    if (n >= NN) return;
#pragma unroll
    for (int c = 0; c < CKDIM; ++c) {
        float v = mk[c * NN + n];
        float v2 = v * v;
        __nv_bfloat16 h = __float2bfloat16(v);
        __nv_bfloat16 h2 = __float2bfloat16(v2);
        g_Mh[(size_t)n * K2 + c]         = h;
        g_Ml[(size_t)n * K2 + c]         = __float2bfloat16(v - __bfloat162float(h));
        g_Mh[(size_t)n * K2 + CKDIM + c] = h2;
        g_Ml[(size_t)n * K2 + CKDIM + c] = __float2bfloat16(v2 - __bfloat162float(h2));
    }
    g_msn[n] = ms[n] * 0.125f;
}

__global__ void prep_mv_kernel(const float* __restrict__ mv) {
    size_t i = (size_t)blockIdx.x * blockDim.x + threadIdx.x;
    float4 v = ((const float4*)mv)[i];
    v.x = tf32r(v.x); v.y = tf32r(v.y); v.z = tf32r(v.z); v.w = tf32r(v.w);
    ((float4*)g_MV)[i] = v;
}

// ---------------- sim kernel: split-bf16 m16n8k16, writes E^T + row partials ------
#define STILE 5120
#define SWORDS 2560

__global__ __launch_bounds__(256, 2) void sim_kernel() {
    extern __shared__ __nv_bfloat16 sm16[];
    const uint32_t* w32 = (const uint32_t*)sm16;
    __shared__ float red[2][128];

    const int tid  = threadIdx.x;
    const int bNn  = blockIdx.x * 128;
    const int bNp  = blockIdx.y * 128;
    const int warp = tid >> 5;
    const int lane = tid & 31;
    const int wm = (warp & 3) * 32;
    const int nw = warp >> 2;
    const int wn = nw * 64;
    const int g  = lane >> 2;
    const int tg = lane & 3;

    float acc[2][8][4];
#pragma unroll
    for (int i = 0; i < 2; ++i)
#pragma unroll
        for (int j = 0; j < 8; ++j)
#pragma unroll
            for (int r = 0; r < 4; ++r) acc[i][j][r] = 0.f;

    const __nv_bfloat16* gsrc[4] = {g_Qh, g_Ql, g_Mh, g_Ml};
    auto load_tiles = [&](int kt, int st) {
#pragma unroll
        for (int t = 0; t < 4; ++t) {
            int rowbase = (t < 2) ? bNp : bNn;
#pragma unroll
            for (int s = 0; s < 2; ++s) {
                int id = tid + s * 256;
                int r  = id >> 2;
                int c  = id & 3;
                uint32_t dst = smem_u32(sm16) +
                               ((t * 2 + st) * STILE + r * 40 + c * 8) * 2;
                cp16(dst, &gsrc[t][(size_t)(rowbase + r) * K2 + kt * 32 + c * 8]);
            }
        }
        asm volatile("cp.async.commit_group;\n" ::);
    };

    load_tiles(0, 0);

    for (int kt = 0; kt < 4; ++kt) {
        const int cur = kt & 1;
        if (kt + 1 < 4) {
            load_tiles(kt + 1, cur ^ 1);
            asm volatile("cp.async.wait_group 1;\n" ::);
        } else {
            asm volatile("cp.async.wait_group 0;\n" ::);
        }
        __syncthreads();

        const int qh = (0 * 2 + cur) * SWORDS;
        const int ql = (1 * 2 + cur) * SWORDS;
        const int mh = (2 * 2 + cur) * SWORDS;
        const int ml = (3 * 2 + cur) * SWORDS;

#pragma unroll
        for (int ks = 0; ks < 2; ++ks) {
            const int k0 = ks * 8;
            uint32_t ah[2][4], al[2][4], bh[8][2], bl[8][2];
#pragma unroll
            for (int i = 0; i < 2; ++i) {
                int r0 = (wm + 16 * i + g) * 20 + k0;
                int r8 = r0 + 8 * 20;
                ah[i][0] = w32[qh + r0 + tg];     ah[i][1] = w32[qh + r8 + tg];
                ah[i][2] = w32[qh + r0 + tg + 4]; ah[i][3] = w32[qh + r8 + tg + 4];
                al[i][0] = w32[ql + r0 + tg];     al[i][1] = w32[ql + r8 + tg];
                al[i][2] = w32[ql + r0 + tg + 4]; al[i][3] = w32[ql + r8 + tg + 4];
            }
#pragma unroll
            for (int j = 0; j < 8; ++j) {
                int nr = (wn + 8 * j + g) * 20 + k0;
                bh[j][0] = w32[mh + nr + tg]; bh[j][1] = w32[mh + nr + tg + 4];
                bl[j][0] = w32[ml + nr + tg]; bl[j][1] = w32[ml + nr + tg + 4];
            }
#pragma unroll
            for (int i = 0; i < 2; ++i)
#pragma unroll
                for (int j = 0; j < 8; ++j) {
                    MMA_BF16(acc[i][j], ah[i], bh[j]);
                    MMA_BF16(acc[i][j], al[i], bh[j]);
                    MMA_BF16(acc[i][j], ah[i], bl[j]);
                }
        }
        __syncthreads();
    }

    float bsqr[2][2];
#pragma unroll
    for (int i = 0; i < 2; ++i) {
        int r0 = bNp + wm + 16 * i + g;
        bsqr[i][0] = g_bsq[r0];
        bsqr[i][1] = g_bsq[r0 + 8];
    }
    float msv[8][2];
#pragma unroll
    for (int j = 0; j < 8; ++j) {
        int c0 = bNn + wn + 8 * j + 2 * tg;
        msv[j][0] = g_msn[c0];
        msv[j][1] = g_msn[c0 + 1];
    }
    float rsum[2][2];
    rsum[0][0] = rsum[0][1] = rsum[1][0] = rsum[1][1] = 0.f;

#pragma unroll
    for (int i = 0; i < 2; ++i) {
        int r0 = bNp + wm + 16 * i + g;
        int r1 = r0 + 8;
#pragma unroll
        for (int j = 0; j < 8; ++j) {
            int c0 = bNn + wn + 8 * j + 2 * tg;
            float e0 = tf32r(__expf(msv[j][0] * (acc[i][j][0] - bsqr[i][0])));
            float e1 = tf32r(__expf(msv[j][1] * (acc[i][j][1] - bsqr[i][0])));
            float e2 = tf32r(__expf(msv[j][0] * (acc[i][j][2] - bsqr[i][1])));
            float e3 = tf32r(__expf(msv[j][1] * (acc[i][j][3] - bsqr[i][1])));
            *(float2*)&g_ST[(size_t)r0 * NN + c0] = make_float2(e0, e1);
            *(float2*)&g_ST[(size_t)r1 * NN + c0] = make_float2(e2, e3);
            rsum[i][0] += e0 + e1;
            rsum[i][1] += e2 + e3;
        }
    }
#pragma unroll
    for (int i = 0; i < 2; ++i)
#pragma unroll
        for (int d = 0; d < 2; ++d) {
            float s = rsum[i][d];
            s += __shfl_xor_sync(0xffffffffu, s, 1);
            s += __shfl_xor_sync(0xffffffffu, s, 2);
            if (tg == 0) red[nw][wm + 16 * i + 8 * d + g] = s;
        }
    __syncthreads();
    if (tid < 128)
        g_part[(size_t)blockIdx.x * NP + bNp + tid] = red[0][tid] + red[1][tid];
}

// ---------------- rinv ----------------
__global__ void rinv_kernel() {
    int p = blockIdx.x * blockDim.x + threadIdx.x;
    float s = 0.f;
#pragma unroll
    for (int b = 0; b < NBLK; ++b) s += g_part[(size_t)b * NP + p];
    g_rinv[p] = 1.0f / s;
}

// ---------------- readout GEMM: tf32 mma.sync + ldmatrix, CTA 128x128 -----------
// out[v][p] = rinv[p] * sum_n MV[v][n] * E^T[p][n]
#define OBK   32
#define ONKT  (NN / OBK)        // 256
#define OAW   36                // row stride in fp32 words (144 B, 16B-aligned)
#define OTSZ  (128 * OAW * 4)   // 18432 B per operand tile
#define OSTG  (2 * OTSZ)        // 36864 B per stage
#define OSMEM (3 * OSTG)        // 110592 B

__global__ __launch_bounds__(256, 2) void out_gemm_kernel(float* __restrict__ out) {
    extern __shared__ float Sf[];
    const int tid  = threadIdx.x;
    const int warp = tid >> 5;
    const int lane = tid & 31;
    const int bM = blockIdx.x * 128;   // v offset (x fastest -> 8 CTAs share B strip)
    const int bN = blockIdx.y * 128;   // p offset
    const int wm = (warp & 3) * 32;    // v warp tile (32)
    const int wn = (warp >> 2) * 64;   // p warp tile (64)
    const int g  = lane >> 2;
    const int tg = lane & 3;
    const uint32_t sbase = smem_u32(Sf);

    // ldmatrix per-thread role offsets (bytes within a stage)
    // A frag i: tiles (rows wm+16i+{0..7}/+8, kcols +0/+4) -> r0..r3 = a0..a3
    uint32_t aoff[2];
#pragma unroll
    for (int i = 0; i < 2; ++i)
        aoff[i] = ((wm + 16 * i + (lane & 15)) * OAW + ((lane & 16) ? 4 : 0)) * 4;
    // B frag pair jp: r0=bf[2jp][0], r1=bf[2jp][1], r2=bf[2jp+1][0], r3=bf[2jp+1][1]
    uint32_t boff[4];
#pragma unroll
    for (int jp = 0; jp < 4; ++jp)
        boff[jp] = OTSZ +
                   ((wn + 16 * jp + ((lane >> 4) & 1) * 8 + (lane & 7)) * OAW +
                    ((lane >> 3) & 1) * 4) * 4;

    float acc[2][8][4];
#pragma unroll
    for (int i = 0; i < 2; ++i)
#pragma unroll
        for (int j = 0; j < 8; ++j)
#pragma unroll
            for (int r = 0; r < 4; ++r) acc[i][j][r] = 0.f;

    auto load_stage = [&](int kt, int st) {
        uint32_t ab = sbase + st * OSTG;
        uint32_t bb = ab + OTSZ;
#pragma unroll
        for (int s = 0; s < 4; ++s) {          // A: 1024 16B chunks
            int id = tid + s * 256;
            int r = id >> 3, c = id & 7;
            cp16(ab + r * 144 + c * 16, &g_MV[(size_t)(bM + r) * NN + kt * OBK + c * 4]);
        }
#pragma unroll
        for (int s = 0; s < 4; ++s) {          // B: 1024 16B chunks
            int id = tid + s * 256;
            int r = id >> 3, c = id & 7;
            cp16(bb + r * 144 + c * 16, &g_ST[(size_t)(bN + r) * NN + kt * OBK + c * 4]);
        }
        asm volatile("cp.async.commit_group;\n" ::);
    };

    load_stage(0, 0);
    load_stage(1, 1);
    load_stage(2, 2);

    for (int kt = 0; kt < ONKT; ++kt) {
        if (kt < ONKT - 2)       asm volatile("cp.async.wait_group 2;\n" ::);
        else if (kt == ONKT - 2) asm volatile("cp.async.wait_group 1;\n" ::);
        else                     asm volatile("cp.async.wait_group 0;\n" ::);
        __syncthreads();

        const uint32_t stb = sbase + (kt % 3) * OSTG;

#pragma unroll
        for (int ks = 0; ks < 4; ++ks) {
            const uint32_t kb = ks * 32;
            uint32_t af[2][4], bf[4][4];
            ldsm4(af[0], stb + aoff[0] + kb);
            ldsm4(af[1], stb + aoff[1] + kb);
#pragma unroll
            for (int jp = 0; jp < 4; ++jp)
                ldsm4(bf[jp], stb + boff[jp] + kb);
#pragma unroll
            for (int i = 0; i < 2; ++i)
#pragma unroll
                for (int jp = 0; jp < 4; ++jp) {
                    MMA_TF32U(acc[i][2 * jp],     af[i], bf[jp][0], bf[jp][1]);
                    MMA_TF32U(acc[i][2 * jp + 1], af[i], bf[jp][2], bf[jp][3]);
                }
        }
        __syncthreads();
        if (kt + 3 < ONKT) load_stage(kt + 3, (kt + 3) % 3);
    }

    // epilogue: scale by rinv[p]
#pragma unroll
    for (int j = 0; j < 8; ++j) {
        int c = bN + wn + 8 * j + 2 * tg;
        float r0 = g_rinv[c];
        float r1 = g_rinv[c + 1];
#pragma unroll
        for (int i = 0; i < 2; ++i) {
            int rr = bM + wm + 16 * i + g;
            *(float2*)&out[(size_t)rr * NP + c] =
                make_float2(acc[i][j][0] * r0, acc[i][j][1] * r1);
            *(float2*)&out[(size_t)(rr + 8) * NP + c] =
                make_float2(acc[i][j][2] * r0, acc[i][j][3] * r1);
        }
    }
}

// ---------------- launch ----------------
extern "C" void kernel_launch(void* const* d_in, const int* in_sizes, int n_in,
                              void* d_out, int out_size) {
    const float* qk = (const float*)d_in[0];
    const float* qe = (const float*)d_in[1];
    const float* mk = (const float*)d_in[2];
    const float* ms = (const float*)d_in[3];
    const float* mv = (const float*)d_in[4];
    float* out = (float*)d_out;

    const int SIM_SMEM = 8 * STILE * 2;   // 81920 B
    cudaFuncSetAttribute(sim_kernel, cudaFuncAttributeMaxDynamicSharedMemorySize, SIM_SMEM);
    cudaFuncSetAttribute(out_gemm_kernel, cudaFuncAttributeMaxDynamicSharedMemorySize, OSMEM);

    prep_q_kernel<<<NP / 256, 256>>>(qk, qe);
    prep_m_kernel<<<NN / 256, 256>>>(mk, ms);
    prep_mv_kernel<<<(NV * NN / 4) / 256, 256>>>(mv);
    sim_kernel<<<dim3(NN / 128, NP / 128), 256, SIM_SMEM>>>();
    rinv_kernel<<<NP / 256, 256>>>();
    out_gemm_kernel<<<dim3(NV / 128, NP / 128), 256, OSMEM>>>(out);
}

// round 10
// speedup vs baseline: 1.5538x; 1.4765x over previous
#include <cuda_runtime.h>
#include <cuda_bf16.h>
#include <cuda_fp16.h>
#include <cstdint>
#include <cstddef>

#define CKDIM 64
#define K2    128
#define NP    4096
#define NN    8192
#define NV    1024
#define NBLK  64

// ---------------- scratch ----------------
__device__ __half g_SH[(size_t)NP * NN];           // E^T[p][n] fp16 (67 MB, K-major)
__device__ __nv_bfloat16 g_Qh[(size_t)NP * K2];
__device__ __nv_bfloat16 g_Ql[(size_t)NP * K2];
__device__ __nv_bfloat16 g_Mh[(size_t)NN * K2];
__device__ __nv_bfloat16 g_Ml[(size_t)NN * K2];
__device__ __half g_MVh[(size_t)NV * NN];          // fp16 mv (16 MB, K-major)
__device__ float g_bsq[NP];
__device__ float g_msn[NN];
__device__ float g_part[(size_t)NBLK * NP];
__device__ float g_rinv[NP];

__device__ __forceinline__ void cp16(uint32_t dst, const void* src) {
    asm volatile("cp.async.cg.shared.global [%0], [%1], 16;\n" :: "r"(dst), "l"(src));
}
__device__ __forceinline__ uint32_t smem_u32(const void* p) {
    return (uint32_t)__cvta_generic_to_shared(p);
}
__device__ __forceinline__ void ldsm4(uint32_t* r, uint32_t addr) {
    asm volatile("ldmatrix.sync.aligned.m8n8.x4.shared.b16 {%0,%1,%2,%3}, [%4];"
                 : "=r"(r[0]), "=r"(r[1]), "=r"(r[2]), "=r"(r[3]) : "r"(addr));
}
#define MMA_BF16U(acc, a, b0, b1)                                                    \
    asm volatile(                                                                    \
        "mma.sync.aligned.m16n8k16.row.col.f32.bf16.bf16.f32 "                       \
        "{%0,%1,%2,%3}, {%4,%5,%6,%7}, {%8,%9}, {%0,%1,%2,%3};\n"                    \
        : "+f"((acc)[0]), "+f"((acc)[1]), "+f"((acc)[2]), "+f"((acc)[3])             \
        : "r"((a)[0]), "r"((a)[1]), "r"((a)[2]), "r"((a)[3]), "r"(b0), "r"(b1))
#define MMA_F16U(acc, a, b0, b1)                                                     \
    asm volatile(                                                                    \
        "mma.sync.aligned.m16n8k16.row.col.f32.f16.f16.f32 "                         \
        "{%0,%1,%2,%3}, {%4,%5,%6,%7}, {%8,%9}, {%0,%1,%2,%3};\n"                    \
        : "+f"((acc)[0]), "+f"((acc)[1]), "+f"((acc)[2]), "+f"((acc)[3])             \
        : "r"((a)[0]), "r"((a)[1]), "r"((a)[2]), "r"((a)[3]), "r"(b0), "r"(b1))

// ---------------- prep kernels ----------------
__global__ void prep_q_kernel(const float* __restrict__ qk, const float* __restrict__ qe) {
    int p = blockIdx.x * blockDim.x + threadIdx.x;
    if (p >= NP) return;
    float bsq = 0.f;
#pragma unroll
    for (int c = 0; c < CKDIM; ++c) {
        float k = qk[c * NP + p];
        float e = qe[c * NP + p];
        float b1 = 2.f * k * e;
        float b2 = -e;
        __nv_bfloat16 h1 = __float2bfloat16(b1);
        __nv_bfloat16 h2 = __float2bfloat16(b2);
        g_Qh[(size_t)p * K2 + c]         = h1;
        g_Ql[(size_t)p * K2 + c]         = __float2bfloat16(b1 - __bfloat162float(h1));
        g_Qh[(size_t)p * K2 + CKDIM + c] = h2;
        g_Ql[(size_t)p * K2 + CKDIM + c] = __float2bfloat16(b2 - __bfloat162float(h2));
        bsq = fmaf(e * k, k, bsq);
    }
    g_bsq[p] = bsq;
}

__global__ void prep_m_kernel(const float* __restrict__ mk, const float* __restrict__ ms) {
    int n = blockIdx.x * blockDim.x + threadIdx.x;
    if (n >= NN) return;
#pragma unroll
    for (int c = 0; c < CKDIM; ++c) {
        float v = mk[c * NN + n];
        float v2 = v * v;
        __nv_bfloat16 h = __float2bfloat16(v);
        __nv_bfloat16 h2 = __float2bfloat16(v2);
        g_Mh[(size_t)n * K2 + c]         = h;
        g_Ml[(size_t)n * K2 + c]         = __float2bfloat16(v - __bfloat162float(h));
        g_Mh[(size_t)n * K2 + CKDIM + c] = h2;
        g_Ml[(size_t)n * K2 + CKDIM + c] = __float2bfloat16(v2 - __bfloat162float(h2));
    }
    g_msn[n] = ms[n] * 0.125f;
}

__global__ void prep_mv_kernel(const float* __restrict__ mv) {
    size_t i = (size_t)blockIdx.x * blockDim.x + threadIdx.x;   // float4 index
    float4 v = ((const float4*)mv)[i];
    __half2 h01 = __floats2half2_rn(v.x, v.y);
    __half2 h23 = __floats2half2_rn(v.z, v.w);
    uint2 pk;
    pk.x = *(uint32_t*)&h01;
    pk.y = *(uint32_t*)&h23;
    ((uint2*)g_MVh)[i] = pk;
}

// ---------------- sim kernel: split-bf16 m16n8k16 + LDSM, writes fp16 E^T ---------
#define STILE 5120          // bf16 elems per tile-stage (128 rows x 40)
__global__ __launch_bounds__(256, 2) void sim_kernel() {
    extern __shared__ __nv_bfloat16 sm16[];
    __shared__ float red[2][128];

    const int tid  = threadIdx.x;
    const int bNn  = blockIdx.x * 128;
    const int bNp  = blockIdx.y * 128;
    const int warp = tid >> 5;
    const int lane = tid & 31;
    const int wm = (warp & 3) * 32;
    const int nw = warp >> 2;
    const int wn = nw * 64;
    const int g  = lane >> 2;
    const int tg = lane & 3;
    const uint32_t sbase = smem_u32(sm16);

    // ldmatrix role offsets (bytes), row stride 80 B
    const uint32_t aoffS = (uint32_t)(wm + (lane & 15)) * 80 + ((lane >> 4) & 1) * 16;
    uint32_t boffS[4];
#pragma unroll
    for (int jp = 0; jp < 4; ++jp)
        boffS[jp] = (uint32_t)(wn + 16 * jp + ((lane >> 4) & 1) * 8 + (lane & 7)) * 80 +
                    ((lane >> 3) & 1) * 16;

    float acc[2][8][4];
#pragma unroll
    for (int i = 0; i < 2; ++i)
#pragma unroll
        for (int j = 0; j < 8; ++j)
#pragma unroll
            for (int r = 0; r < 4; ++r) acc[i][j][r] = 0.f;

    const __nv_bfloat16* gsrc[4] = {g_Qh, g_Ql, g_Mh, g_Ml};
    auto load_tiles = [&](int kt, int st) {
#pragma unroll
        for (int t = 0; t < 4; ++t) {
            int rowbase = (t < 2) ? bNp : bNn;
#pragma unroll
            for (int s = 0; s < 2; ++s) {
                int id = tid + s * 256;
                int r  = id >> 2;
                int c  = id & 3;
                uint32_t dst = sbase + ((t * 2 + st) * STILE + r * 40 + c * 8) * 2;
                cp16(dst, &gsrc[t][(size_t)(rowbase + r) * K2 + kt * 32 + c * 8]);
            }
        }
        asm volatile("cp.async.commit_group;\n" ::);
    };

    load_tiles(0, 0);

    for (int kt = 0; kt < 4; ++kt) {
        const int cur = kt & 1;
        if (kt + 1 < 4) {
            load_tiles(kt + 1, cur ^ 1);
            asm volatile("cp.async.wait_group 1;\n" ::);
        } else {
            asm volatile("cp.async.wait_group 0;\n" ::);
        }
        __syncthreads();

        const uint32_t qhB = sbase + (0 * 2 + cur) * STILE * 2;
        const uint32_t qlB = sbase + (1 * 2 + cur) * STILE * 2;
        const uint32_t mhB = sbase + (2 * 2 + cur) * STILE * 2;
        const uint32_t mlB = sbase + (3 * 2 + cur) * STILE * 2;

#pragma unroll
        for (int ks = 0; ks < 2; ++ks) {
            const uint32_t kb = ks * 32;
            uint32_t ah[2][4], al[2][4], bh[4][4], bl[4][4];
            ldsm4(ah[0], qhB + aoffS + kb);
            ldsm4(ah[1], qhB + aoffS + 1280 + kb);
            ldsm4(al[0], qlB + aoffS + kb);
            ldsm4(al[1], qlB + aoffS + 1280 + kb);
#pragma unroll
            for (int jp = 0; jp < 4; ++jp) {
                ldsm4(bh[jp], mhB + boffS[jp] + kb);
                ldsm4(bl[jp], mlB + boffS[jp] + kb);
            }
#pragma unroll
            for (int i = 0; i < 2; ++i)
#pragma unroll
                for (int jp = 0; jp < 4; ++jp) {
                    MMA_BF16U(acc[i][2 * jp],     ah[i], bh[jp][0], bh[jp][1]);
                    MMA_BF16U(acc[i][2 * jp],     al[i], bh[jp][0], bh[jp][1]);
                    MMA_BF16U(acc[i][2 * jp],     ah[i], bl[jp][0], bl[jp][1]);
                    MMA_BF16U(acc[i][2 * jp + 1], ah[i], bh[jp][2], bh[jp][3]);
                    MMA_BF16U(acc[i][2 * jp + 1], al[i], bh[jp][2], bh[jp][3]);
                    MMA_BF16U(acc[i][2 * jp + 1], ah[i], bl[jp][2], bl[jp][3]);
                }
        }
        __syncthreads();
    }

    // epilogue: e = exp(msn[n]*(acc - bsq[p])), fp16-round, write E^T, row sums per p
    float bsqr[2][2];
#pragma unroll
    for (int i = 0; i < 2; ++i) {
        int r0 = bNp + wm + 16 * i + g;
        bsqr[i][0] = g_bsq[r0];
        bsqr[i][1] = g_bsq[r0 + 8];
    }
    float msv[8][2];
#pragma unroll
    for (int j = 0; j < 8; ++j) {
        int c0 = bNn + wn + 8 * j + 2 * tg;
        msv[j][0] = g_msn[c0];
        msv[j][1] = g_msn[c0 + 1];
    }
    float rsum[2][2];
    rsum[0][0] = rsum[0][1] = rsum[1][0] = rsum[1][1] = 0.f;

#pragma unroll
    for (int i = 0; i < 2; ++i) {
        int r0 = bNp + wm + 16 * i + g;
        int r1 = r0 + 8;
#pragma unroll
        for (int j = 0; j < 8; ++j) {
            int c0 = bNn + wn + 8 * j + 2 * tg;
            __half h0 = __float2half_rn(__expf(msv[j][0] * (acc[i][j][0] - bsqr[i][0])));
            __half h1 = __float2half_rn(__expf(msv[j][1] * (acc[i][j][1] - bsqr[i][0])));
            __half h2 = __float2half_rn(__expf(msv[j][0] * (acc[i][j][2] - bsqr[i][1])));
            __half h3 = __float2half_rn(__expf(msv[j][1] * (acc[i][j][3] - bsqr[i][1])));
            *(__half2*)&g_SH[(size_t)r0 * NN + c0] = __halves2half2(h0, h1);
            *(__half2*)&g_SH[(size_t)r1 * NN + c0] = __halves2half2(h2, h3);
            rsum[i][0] += __half2float(h0) + __half2float(h1);
            rsum[i][1] += __half2float(h2) + __half2float(h3);
        }
    }
#pragma unroll
    for (int i = 0; i < 2; ++i)
#pragma unroll
        for (int d = 0; d < 2; ++d) {
            float s = rsum[i][d];
            s += __shfl_xor_sync(0xffffffffu, s, 1);
            s += __shfl_xor_sync(0xffffffffu, s, 2);
            if (tg == 0) red[nw][wm + 16 * i + 8 * d + g] = s;
        }
    __syncthreads();
    if (tid < 128)
        g_part[(size_t)blockIdx.x * NP + bNp + tid] = red[0][tid] + red[1][tid];
}

// ---------------- rinv ----------------
__global__ void rinv_kernel() {
    int p = blockIdx.x * blockDim.x + threadIdx.x;
    float s = 0.f;
#pragma unroll
    for (int b = 0; b < NBLK; ++b) s += g_part[(size_t)b * NP + p];
    g_rinv[p] = 1.0f / s;
}

// ---------------- readout GEMM: fp16 m16n8k16 + LDSM, CTA 128x128, BK=64 --------
// out[v][p] = rinv[p] * sum_n MVh[v][n] * E^T[p][n]
#define OBK   64
#define ONKT  (NN / OBK)        // 128
#define ORS   144               // row stride bytes (64 fp16 data + 8 pad)
#define OTSZ  (128 * ORS)       // 18432 B per operand tile
#define OSTG  (2 * OTSZ)        // 36864 B per stage
#define OSMEM (3 * OSTG)        // 110592 B

__global__ __launch_bounds__(256, 2) void out_gemm_kernel(float* __restrict__ out) {
    extern __shared__ __half Sh[];
    const int tid  = threadIdx.x;
    const int warp = tid >> 5;
    const int lane = tid & 31;
    const int bM = blockIdx.x * 128;   // v offset (x fastest -> 8 CTAs share E strip)
    const int bN = blockIdx.y * 128;   // p offset
    const int wm = (warp & 3) * 32;
    const int wn = (warp >> 2) * 64;
    const int g  = lane >> 2;
    const int tg = lane & 3;
    const uint32_t sbase = smem_u32(Sh);

    uint32_t aoff[2];
#pragma unroll
    for (int i = 0; i < 2; ++i)
        aoff[i] = (uint32_t)(wm + 16 * i + (lane & 15)) * ORS + ((lane >> 4) & 1) * 16;
    uint32_t boff[4];
#pragma unroll
    for (int jp = 0; jp < 4; ++jp)
        boff[jp] = OTSZ +
                   (uint32_t)(wn + 16 * jp + ((lane >> 4) & 1) * 8 + (lane & 7)) * ORS +
                   ((lane >> 3) & 1) * 16;

    float acc[2][8][4];
#pragma unroll
    for (int i = 0; i < 2; ++i)
#pragma unroll
        for (int j = 0; j < 8; ++j)
#pragma unroll
            for (int r = 0; r < 4; ++r) acc[i][j][r] = 0.f;

    auto load_stage = [&](int kt, int st) {
        uint32_t ab = sbase + st * OSTG;
        uint32_t bb = ab + OTSZ;
#pragma unroll
        for (int s = 0; s < 4; ++s) {          // A: 1024 16B chunks (128 rows x 8)
            int id = tid + s * 256;
            int r = id >> 3, c = id & 7;
            cp16(ab + r * ORS + c * 16, &g_MVh[(size_t)(bM + r) * NN + kt * OBK + c * 8]);
        }
#pragma unroll
        for (int s = 0; s < 4; ++s) {          // B: 1024 16B chunks
            int id = tid + s * 256;
            int r = id >> 3, c = id & 7;
            cp16(bb + r * ORS + c * 16, &g_SH[(size_t)(bN + r) * NN + kt * OBK + c * 8]);
        }
        asm volatile("cp.async.commit_group;\n" ::);
    };

    load_stage(0, 0);
    load_stage(1, 1);
    load_stage(2, 2);

    for (int kt = 0; kt < ONKT; ++kt) {
        if (kt < ONKT - 2)       asm volatile("cp.async.wait_group 2;\n" ::);
        else if (kt == ONKT - 2) asm volatile("cp.async.wait_group 1;\n" ::);
        else                     asm volatile("cp.async.wait_group 0;\n" ::);
        __syncthreads();

        const uint32_t stb = sbase + (kt % 3) * OSTG;

#pragma unroll
        for (int ks = 0; ks < 4; ++ks) {       // 4 x k16
            const uint32_t kb = ks * 32;
            uint32_t af[2][4], bf[4][4];
            ldsm4(af[0], stb + aoff[0] + kb);
            ldsm4(af[1], stb + aoff[1] + kb);
#pragma unroll
            for (int jp = 0; jp < 4; ++jp)
                ldsm4(bf[jp], stb + boff[jp] + kb);
#pragma unroll
            for (int i = 0; i < 2; ++i)
#pragma unroll
                for (int jp = 0; jp < 4; ++jp) {
                    MMA_F16U(acc[i][2 * jp],     af[i], bf[jp][0], bf[jp][1]);
                    MMA_F16U(acc[i][2 * jp + 1], af[i], bf[jp][2], bf[jp][3]);
                }
        }
        __syncthreads();
        if (kt + 3 < ONKT) load_stage(kt + 3, (kt + 3) % 3);
    }

    // epilogue: scale by rinv[p]
#pragma unroll
    for (int j = 0; j < 8; ++j) {
        int c = bN + wn + 8 * j + 2 * tg;
        float r0 = g_rinv[c];
        float r1 = g_rinv[c + 1];
#pragma unroll
        for (int i = 0; i < 2; ++i) {
            int rr = bM + wm + 16 * i + g;
            *(float2*)&out[(size_t)rr * NP + c] =
                make_float2(acc[i][j][0] * r0, acc[i][j][1] * r1);
            *(float2*)&out[(size_t)(rr + 8) * NP + c] =
                make_float2(acc[i][j][2] * r0, acc[i][j][3] * r1);
        }
    }
}

// ---------------- launch ----------------
extern "C" void kernel_launch(void* const* d_in, const int* in_sizes, int n_in,
                              void* d_out, int out_size) {
    const float* qk = (const float*)d_in[0];
    const float* qe = (const float*)d_in[1];
    const float* mk = (const float*)d_in[2];
    const float* ms = (const float*)d_in[3];
    const float* mv = (const float*)d_in[4];
    float* out = (float*)d_out;

    const int SIM_SMEM = 8 * STILE * 2;   // 81920 B
    cudaFuncSetAttribute(sim_kernel, cudaFuncAttributeMaxDynamicSharedMemorySize, SIM_SMEM);
    cudaFuncSetAttribute(out_gemm_kernel, cudaFuncAttributeMaxDynamicSharedMemorySize, OSMEM);

    prep_q_kernel<<<NP / 256, 256>>>(qk, qe);
    prep_m_kernel<<<NN / 256, 256>>>(mk, ms);
    prep_mv_kernel<<<(NV * NN / 4) / 256, 256>>>(mv);
    sim_kernel<<<dim3(NN / 128, NP / 128), 256, SIM_SMEM>>>();
    rinv_kernel<<<NP / 256, 256>>>();
    out_gemm_kernel<<<dim3(NV / 128, NP / 128), 256, OSMEM>>>(out);
}

// round 11
// speedup vs baseline: 2.0539x; 1.3219x over previous
#include <cuda_runtime.h>
#include <cuda_fp16.h>
#include <cstdint>
#include <cstddef>

#define CKDIM 64
#define K2    128
#define NP    4096
#define NN    8192
#define NV    1024
#define NBLK  64

// ---------------- scratch ----------------
__device__ __half g_SH[(size_t)NP * NN];           // E^T[p][n] fp16 (67 MB, K-major)
__device__ __half g_QH[(size_t)NP * K2];           // [p][k] fp16 [2qk*qe; -qe]
__device__ __half g_MH[(size_t)NN * K2];           // [n][k] fp16 [mk; mk^2]
__device__ __half g_MVh[(size_t)NV * NN];          // fp16 mv (16 MB, K-major)
__device__ float g_bsq[NP];
__device__ float g_msn[NN];
__device__ float g_part[(size_t)NBLK * NP];
__device__ float g_rinv[NP];

__device__ __forceinline__ void cp16(uint32_t dst, const void* src) {
    asm volatile("cp.async.cg.shared.global [%0], [%1], 16;\n" :: "r"(dst), "l"(src));
}
__device__ __forceinline__ uint32_t smem_u32(const void* p) {
    return (uint32_t)__cvta_generic_to_shared(p);
}
__device__ __forceinline__ void ldsm4(uint32_t* r, uint32_t addr) {
    asm volatile("ldmatrix.sync.aligned.m8n8.x4.shared.b16 {%0,%1,%2,%3}, [%4];"
                 : "=r"(r[0]), "=r"(r[1]), "=r"(r[2]), "=r"(r[3]) : "r"(addr));
}
#define MMA_F16U(acc, a, b0, b1)                                                     \
    asm volatile(                                                                    \
        "mma.sync.aligned.m16n8k16.row.col.f32.f16.f16.f32 "                         \
        "{%0,%1,%2,%3}, {%4,%5,%6,%7}, {%8,%9}, {%0,%1,%2,%3};\n"                    \
        : "+f"((acc)[0]), "+f"((acc)[1]), "+f"((acc)[2]), "+f"((acc)[3])             \
        : "r"((a)[0]), "r"((a)[1]), "r"((a)[2]), "r"((a)[3]), "r"(b0), "r"(b1))

// row stride for all GEMM smem tiles: 64 fp16 data + 8 pad = 144 B
#define RS    144
#define TSZ   (128 * RS)      // 18432 B per operand tile

// ---------------- prep kernels ----------------
__global__ void prep_q_kernel(const float* __restrict__ qk, const float* __restrict__ qe) {
    int p = blockIdx.x * blockDim.x + threadIdx.x;
    if (p >= NP) return;
    float bsq = 0.f;
#pragma unroll
    for (int c = 0; c < CKDIM; ++c) {
        float k = qk[c * NP + p];
        float e = qe[c * NP + p];
        g_QH[(size_t)p * K2 + c]         = __float2half_rn(2.f * k * e);
        g_QH[(size_t)p * K2 + CKDIM + c] = __float2half_rn(-e);
        bsq = fmaf(e * k, k, bsq);
    }
    g_bsq[p] = bsq;
}

__global__ void prep_m_kernel(const float* __restrict__ mk, const float* __restrict__ ms) {
    int n = blockIdx.x * blockDim.x + threadIdx.x;
    if (n >= NN) return;
#pragma unroll
    for (int c = 0; c < CKDIM; ++c) {
        float v = mk[c * NN + n];
        g_MH[(size_t)n * K2 + c]         = __float2half_rn(v);
        g_MH[(size_t)n * K2 + CKDIM + c] = __float2half_rn(v * v);
    }
    g_msn[n] = ms[n] * 0.125f;
}

__global__ void prep_mv_kernel(const float* __restrict__ mv) {
    size_t i = (size_t)blockIdx.x * blockDim.x + threadIdx.x;   // float4 index
    float4 v = ((const float4*)mv)[i];
    __half2 h01 = __floats2half2_rn(v.x, v.y);
    __half2 h23 = __floats2half2_rn(v.z, v.w);
    uint2 pk;
    pk.x = *(uint32_t*)&h01;
    pk.y = *(uint32_t*)&h23;
    ((uint2*)g_MVh)[i] = pk;
}

// ---------------- sim kernel: 1-term fp16 m16n8k16 + LDSM, writes fp16 E^T --------
// D[p][n]: A=Q[p][k] (128 rows), B=M[n][k] (128 cols). K2=128 in 2 chunks of 64.
#define SSTG  (2 * TSZ)       // stage = Q tile + M tile = 36864 B
#define SSMEM (2 * SSTG)      // 73728 B

__global__ __launch_bounds__(256, 2) void sim_kernel() {
    extern __shared__ __half sh[];
    __shared__ float red[2][128];

    const int tid  = threadIdx.x;
    const int bNn  = blockIdx.x * 128;   // n offset
    const int bNp  = blockIdx.y * 128;   // p offset
    const int warp = tid >> 5;
    const int lane = tid & 31;
    const int wm = (warp & 3) * 32;      // p warp tile
    const int nw = warp >> 2;
    const int wn = nw * 64;              // n warp tile
    const int g  = lane >> 2;
    const int tg = lane & 3;
    const uint32_t sbase = smem_u32(sh);

    uint32_t aoff[2];
#pragma unroll
    for (int i = 0; i < 2; ++i)
        aoff[i] = (uint32_t)(wm + 16 * i + (lane & 15)) * RS + ((lane >> 4) & 1) * 16;
    uint32_t boff[4];
#pragma unroll
    for (int jp = 0; jp < 4; ++jp)
        boff[jp] = TSZ +
                   (uint32_t)(wn + 16 * jp + ((lane >> 4) & 1) * 8 + (lane & 7)) * RS +
                   ((lane >> 3) & 1) * 16;

    float acc[2][8][4];
#pragma unroll
    for (int i = 0; i < 2; ++i)
#pragma unroll
        for (int j = 0; j < 8; ++j)
#pragma unroll
            for (int r = 0; r < 4; ++r) acc[i][j][r] = 0.f;

    auto load_stage = [&](int kt, int st) {
        uint32_t ab = sbase + st * SSTG;
        uint32_t bb = ab + TSZ;
#pragma unroll
        for (int s = 0; s < 4; ++s) {          // Q: 1024 16B chunks
            int id = tid + s * 256;
            int r = id >> 3, c = id & 7;
            cp16(ab + r * RS + c * 16, &g_QH[(size_t)(bNp + r) * K2 + kt * 64 + c * 8]);
        }
#pragma unroll
        for (int s = 0; s < 4; ++s) {          // M: 1024 16B chunks
            int id = tid + s * 256;
            int r = id >> 3, c = id & 7;
            cp16(bb + r * RS + c * 16, &g_MH[(size_t)(bNn + r) * K2 + kt * 64 + c * 8]);
        }
        asm volatile("cp.async.commit_group;\n" ::);
    };

    load_stage(0, 0);
    load_stage(1, 1);

#pragma unroll
    for (int kt = 0; kt < 2; ++kt) {
        if (kt == 0) asm volatile("cp.async.wait_group 1;\n" ::);
        else         asm volatile("cp.async.wait_group 0;\n" ::);
        __syncthreads();
        const uint32_t stb = sbase + kt * SSTG;
#pragma unroll
        for (int ks = 0; ks < 4; ++ks) {
            const uint32_t kb = ks * 32;
            uint32_t af[2][4], bf[4][4];
            ldsm4(af[0], stb + aoff[0] + kb);
            ldsm4(af[1], stb + aoff[1] + kb);
#pragma unroll
            for (int jp = 0; jp < 4; ++jp)
                ldsm4(bf[jp], stb + boff[jp] + kb);
#pragma unroll
            for (int i = 0; i < 2; ++i)
#pragma unroll
                for (int jp = 0; jp < 4; ++jp) {
                    MMA_F16U(acc[i][2 * jp],     af[i], bf[jp][0], bf[jp][1]);
                    MMA_F16U(acc[i][2 * jp + 1], af[i], bf[jp][2], bf[jp][3]);
                }
        }
    }

    // epilogue: e = exp(msn[n]*(acc - bsq[p])), fp16-round, write E^T, row sums per p
    float bsqr[2][2];
#pragma unroll
    for (int i = 0; i < 2; ++i) {
        int r0 = bNp + wm + 16 * i + g;
        bsqr[i][0] = g_bsq[r0];
        bsqr[i][1] = g_bsq[r0 + 8];
    }
    float msv[8][2];
#pragma unroll
    for (int j = 0; j < 8; ++j) {
        int c0 = bNn + wn + 8 * j + 2 * tg;
        msv[j][0] = g_msn[c0];
        msv[j][1] = g_msn[c0 + 1];
    }
    float rsum[2][2];
    rsum[0][0] = rsum[0][1] = rsum[1][0] = rsum[1][1] = 0.f;

#pragma unroll
    for (int i = 0; i < 2; ++i) {
        int r0 = bNp + wm + 16 * i + g;
        int r1 = r0 + 8;
#pragma unroll
        for (int j = 0; j < 8; ++j) {
            int c0 = bNn + wn + 8 * j + 2 * tg;
            __half h0 = __float2half_rn(__expf(msv[j][0] * (acc[i][j][0] - bsqr[i][0])));
            __half h1 = __float2half_rn(__expf(msv[j][1] * (acc[i][j][1] - bsqr[i][0])));
            __half h2 = __float2half_rn(__expf(msv[j][0] * (acc[i][j][2] - bsqr[i][1])));
            __half h3 = __float2half_rn(__expf(msv[j][1] * (acc[i][j][3] - bsqr[i][1])));
            *(__half2*)&g_SH[(size_t)r0 * NN + c0] = __halves2half2(h0, h1);
            *(__half2*)&g_SH[(size_t)r1 * NN + c0] = __halves2half2(h2, h3);
            rsum[i][0] += __half2float(h0) + __half2float(h1);
            rsum[i][1] += __half2float(h2) + __half2float(h3);
        }
    }
#pragma unroll
    for (int i = 0; i < 2; ++i)
#pragma unroll
        for (int d = 0; d < 2; ++d) {
            float s = rsum[i][d];
            s += __shfl_xor_sync(0xffffffffu, s, 1);
            s += __shfl_xor_sync(0xffffffffu, s, 2);
            if (tg == 0) red[nw][wm + 16 * i + 8 * d + g] = s;
        }
    __syncthreads();
    if (tid < 128)
        g_part[(size_t)blockIdx.x * NP + bNp + tid] = red[0][tid] + red[1][tid];
}

// ---------------- rinv ----------------
__global__ void rinv_kernel() {
    int p = blockIdx.x * blockDim.x + threadIdx.x;
    float s = 0.f;
#pragma unroll
    for (int b = 0; b < NBLK; ++b) s += g_part[(size_t)b * NP + p];
    g_rinv[p] = 1.0f / s;
}

// ---------------- readout GEMM: fp16 m16n8k16 + LDSM, single-barrier pipeline ----
// out[v][p] = rinv[p] * sum_n MVh[v][n] * E^T[p][n]
#define OBK   64
#define ONKT  (NN / OBK)        // 128
#define OSTG  (2 * TSZ)         // 36864 B per stage
#define OSMEM (3 * OSTG)        // 110592 B

__global__ __launch_bounds__(256, 2) void out_gemm_kernel(float* __restrict__ out) {
    extern __shared__ __half Sh[];
    const int tid  = threadIdx.x;
    const int warp = tid >> 5;
    const int lane = tid & 31;
    const int bM = blockIdx.x * 128;   // v offset (x fastest -> 8 CTAs share E strip)
    const int bN = blockIdx.y * 128;   // p offset
    const int wm = (warp & 3) * 32;
    const int wn = (warp >> 2) * 64;
    const int g  = lane >> 2;
    const int tg = lane & 3;
    const uint32_t sbase = smem_u32(Sh);

    uint32_t aoff[2];
#pragma unroll
    for (int i = 0; i < 2; ++i)
        aoff[i] = (uint32_t)(wm + 16 * i + (lane & 15)) * RS + ((lane >> 4) & 1) * 16;
    uint32_t boff[4];
#pragma unroll
    for (int jp = 0; jp < 4; ++jp)
        boff[jp] = TSZ +
                   (uint32_t)(wn + 16 * jp + ((lane >> 4) & 1) * 8 + (lane & 7)) * RS +
                   ((lane >> 3) & 1) * 16;

    float acc[2][8][4];
#pragma unroll
    for (int i = 0; i < 2; ++i)
#pragma unroll
        for (int j = 0; j < 8; ++j)
#pragma unroll
            for (int r = 0; r < 4; ++r) acc[i][j][r] = 0.f;

    auto load_stage = [&](int kt, int st) {
        uint32_t ab = sbase + st * OSTG;
        uint32_t bb = ab + TSZ;
#pragma unroll
        for (int s = 0; s < 4; ++s) {          // A: 1024 16B chunks
            int id = tid + s * 256;
            int r = id >> 3, c = id & 7;
            cp16(ab + r * RS + c * 16, &g_MVh[(size_t)(bM + r) * NN + kt * OBK + c * 8]);
        }
#pragma unroll
        for (int s = 0; s < 4; ++s) {          // B: 1024 16B chunks
            int id = tid + s * 256;
            int r = id >> 3, c = id & 7;
            cp16(bb + r * RS + c * 16, &g_SH[(size_t)(bN + r) * NN + kt * OBK + c * 8]);
        }
        asm volatile("cp.async.commit_group;\n" ::);
    };

    load_stage(0, 0);
    load_stage(1, 1);

    for (int kt = 0; kt < ONKT; ++kt) {
        if (kt + 1 < ONKT) asm volatile("cp.async.wait_group 1;\n" ::);
        else               asm volatile("cp.async.wait_group 0;\n" ::);
        __syncthreads();
        if (kt + 2 < ONKT) load_stage(kt + 2, (kt + 2) % 3);  // overwrites stage drained at kt-1

        const uint32_t stb = sbase + (kt % 3) * OSTG;
#pragma unroll
        for (int ks = 0; ks < 4; ++ks) {       // 4 x k16
            const uint32_t kb = ks * 32;
            uint32_t af[2][4], bf[4][4];
            ldsm4(af[0], stb + aoff[0] + kb);
            ldsm4(af[1], stb + aoff[1] + kb);
#pragma unroll
            for (int jp = 0; jp < 4; ++jp)
                ldsm4(bf[jp], stb + boff[jp] + kb);
#pragma unroll
            for (int i = 0; i < 2; ++i)
#pragma unroll
                for (int jp = 0; jp < 4; ++jp) {
                    MMA_F16U(acc[i][2 * jp],     af[i], bf[jp][0], bf[jp][1]);
                    MMA_F16U(acc[i][2 * jp + 1], af[i], bf[jp][2], bf[jp][3]);
                }
        }
    }

    // epilogue: scale by rinv[p]
#pragma unroll
    for (int j = 0; j < 8; ++j) {
        int c = bN + wn + 8 * j + 2 * tg;
        float r0 = g_rinv[c];
        float r1 = g_rinv[c + 1];
#pragma unroll
        for (int i = 0; i < 2; ++i) {
            int rr = bM + wm + 16 * i + g;
            *(float2*)&out[(size_t)rr * NP + c] =
                make_float2(acc[i][j][0] * r0, acc[i][j][1] * r1);
            *(float2*)&out[(size_t)(rr + 8) * NP + c] =
                make_float2(acc[i][j][2] * r0, acc[i][j][3] * r1);
        }
    }
}

// ---------------- launch ----------------
extern "C" void kernel_launch(void* const* d_in, const int* in_sizes, int n_in,
                              void* d_out, int out_size) {
    const float* qk = (const float*)d_in[0];
    const float* qe = (const float*)d_in[1];
    const float* mk = (const float*)d_in[2];
    const float* ms = (const float*)d_in[3];
    const float* mv = (const float*)d_in[4];
    float* out = (float*)d_out;

    cudaFuncSetAttribute(sim_kernel, cudaFuncAttributeMaxDynamicSharedMemorySize, SSMEM);
    cudaFuncSetAttribute(out_gemm_kernel, cudaFuncAttributeMaxDynamicSharedMemorySize, OSMEM);

    prep_q_kernel<<<NP / 256, 256>>>(qk, qe);
    prep_m_kernel<<<NN / 256, 256>>>(mk, ms);
    prep_mv_kernel<<<(NV * NN / 4) / 256, 256>>>(mv);
    sim_kernel<<<dim3(NN / 128, NP / 128), 256, SSMEM>>>();
    rinv_kernel<<<NP / 256, 256>>>();
    out_gemm_kernel<<<dim3(NV / 128, NP / 128), 256, OSMEM>>>(out);
}

// round 13
// speedup vs baseline: 2.3544x; 1.1463x over previous
#include <cuda_runtime.h>
#include <cuda_fp16.h>
#include <cstdint>
#include <cstddef>

#define CKDIM 64
#define K2    128
#define NP    4096
#define NN    8192
#define NV    1024
#define NBLK  64

// ---------------- scratch ----------------
__device__ __half g_SH[(size_t)NP * NN];           // E^T[p][n] fp16 (67 MB, K-major)
__device__ __half g_QH[(size_t)NP * K2];           // [p][k] fp16 [2qk*qe; -qe]
__device__ __half g_MH[(size_t)NN * K2];           // [n][k] fp16 [mk; mk^2]
__device__ __half g_MVh[(size_t)NV * NN];          // fp16 mv (16 MB, K-major)
__device__ float g_bsq[NP];
__device__ float g_msn[NN];
__device__ float g_part[(size_t)NBLK * NP];
__device__ float g_rinv[NP];

__device__ __forceinline__ void cp16(uint32_t dst, const void* src) {
    asm volatile("cp.async.cg.shared.global [%0], [%1], 16;\n" :: "r"(dst), "l"(src));
}
__device__ __forceinline__ uint32_t smem_u32(const void* p) {
    return (uint32_t)__cvta_generic_to_shared(p);
}
__device__ __forceinline__ void ldsm4(uint32_t* r, uint32_t addr) {
    asm volatile("ldmatrix.sync.aligned.m8n8.x4.shared.b16 {%0,%1,%2,%3}, [%4];"
                 : "=r"(r[0]), "=r"(r[1]), "=r"(r[2]), "=r"(r[3]) : "r"(addr));
}
#define MMA_F16U(acc, a, b0, b1)                                                     \
    asm volatile(                                                                    \
        "mma.sync.aligned.m16n8k16.row.col.f32.f16.f16.f32 "                         \
        "{%0,%1,%2,%3}, {%4,%5,%6,%7}, {%8,%9}, {%0,%1,%2,%3};\n"                    \
        : "+f"((acc)[0]), "+f"((acc)[1]), "+f"((acc)[2]), "+f"((acc)[3])             \
        : "r"((a)[0]), "r"((a)[1]), "r"((a)[2]), "r"((a)[3]), "r"(b0), "r"(b1))
#define CP_COMMIT()  asm volatile("cp.async.commit_group;\n" ::)
#define CP_WAIT(N)   asm volatile("cp.async.wait_group %0;\n" :: "n"(N))

// row stride for all GEMM smem tiles: 64 fp16 data + 8 pad = 144 B
#define RS    144
#define TSZ   (128 * RS)      // 18432 B per operand tile

// ---------------- prep kernels ----------------
__global__ void prep_q_kernel(const float* __restrict__ qk, const float* __restrict__ qe) {
    int p = blockIdx.x * blockDim.x + threadIdx.x;
    if (p >= NP) return;
    float bsq = 0.f;
#pragma unroll
    for (int c = 0; c < CKDIM; ++c) {
        float k = qk[c * NP + p];
        float e = qe[c * NP + p];
        g_QH[(size_t)p * K2 + c]         = __float2half_rn(2.f * k * e);
        g_QH[(size_t)p * K2 + CKDIM + c] = __float2half_rn(-e);
        bsq = fmaf(e * k, k, bsq);
    }
    g_bsq[p] = bsq;
}

__global__ void prep_m_kernel(const float* __restrict__ mk, const float* __restrict__ ms) {
    int n = blockIdx.x * blockDim.x + threadIdx.x;
    if (n >= NN) return;
#pragma unroll
    for (int c = 0; c < CKDIM; ++c) {
        float v = mk[c * NN + n];
        g_MH[(size_t)n * K2 + c]         = __float2half_rn(v);
        g_MH[(size_t)n * K2 + CKDIM + c] = __float2half_rn(v * v);
    }
    g_msn[n] = ms[n] * 0.125f;
}

__global__ void prep_mv_kernel(const float* __restrict__ mv) {
    size_t i = (size_t)blockIdx.x * blockDim.x + threadIdx.x;   // float4 index
    float4 v = ((const float4*)mv)[i];
    __half2 h01 = __floats2half2_rn(v.x, v.y);
    __half2 h23 = __floats2half2_rn(v.z, v.w);
    uint2 pk;
    pk.x = *(uint32_t*)&h01;
    pk.y = *(uint32_t*)&h23;
    ((uint2*)g_MVh)[i] = pk;
}

// ---------------- sim kernel: fp16 m16n8k16, 2 n-tiles per CTA, resident Q -------
// grid (32, 32): x = n-pair (256 n), y = p-tile (128 p).
// smem: Q[k0] | Q[k1] | M0 | M1 | M2 (ring)   (5 * TSZ = 92160 B)
#define SSMEM (5 * TSZ)

__global__ __launch_bounds__(256, 2) void sim_kernel() {
    extern __shared__ __half sh[];
    __shared__ float red[2][128];

    const int tid  = threadIdx.x;
    const int bNp  = blockIdx.y * 128;       // p offset
    const int nb0  = blockIdx.x * 256;       // first n tile
    const int warp = tid >> 5;
    const int lane = tid & 31;
    const int wm = (warp & 3) * 32;          // p warp tile
    const int nw = warp >> 2;
    const int wn = nw * 64;                  // n warp tile
    const int g  = lane >> 2;
    const int tg = lane & 3;
    const uint32_t sbase = smem_u32(sh);
    const uint32_t QB0 = sbase;
    const uint32_t QB1 = sbase + TSZ;
    const uint32_t MB[3] = {sbase + 2 * TSZ, sbase + 3 * TSZ, sbase + 4 * TSZ};

    uint32_t aoff[2];
#pragma unroll
    for (int i = 0; i < 2; ++i)
        aoff[i] = (uint32_t)(wm + 16 * i + (lane & 15)) * RS + ((lane >> 4) & 1) * 16;
    uint32_t boff[4];
#pragma unroll
    for (int jp = 0; jp < 4; ++jp)
        boff[jp] = (uint32_t)(wn + 16 * jp + ((lane >> 4) & 1) * 8 + (lane & 7)) * RS +
                   ((lane >> 3) & 1) * 16;

    float acc[2][8][4];

    auto load_q = [&](int kt) {
        uint32_t ab = sbase + kt * TSZ;
#pragma unroll
        for (int s = 0; s < 4; ++s) {
            int id = tid + s * 256;
            int r = id >> 3, c = id & 7;
            cp16(ab + r * RS + c * 16, &g_QH[(size_t)(bNp + r) * K2 + kt * 64 + c * 8]);
        }
    };
    auto load_m = [&](int nt, int kt, int buf) {
        uint32_t mb = MB[buf];
        int bNn = nb0 + nt * 128;
#pragma unroll
        for (int s = 0; s < 4; ++s) {
            int id = tid + s * 256;
            int r = id >> 3, c = id & 7;
            cp16(mb + r * RS + c * 16, &g_MH[(size_t)(bNn + r) * K2 + kt * 64 + c * 8]);
        }
    };
    auto mma_step = [&](uint32_t qb, uint32_t mb) {
#pragma unroll
        for (int ks = 0; ks < 4; ++ks) {
            const uint32_t kb = ks * 32;
            uint32_t af[2][4], bf[4][4];
            ldsm4(af[0], qb + aoff[0] + kb);
            ldsm4(af[1], qb + aoff[1] + kb);
#pragma unroll
            for (int jp = 0; jp < 4; ++jp)
                ldsm4(bf[jp], mb + boff[jp] + kb);
#pragma unroll
            for (int i = 0; i < 2; ++i)
#pragma unroll
                for (int jp = 0; jp < 4; ++jp) {
                    MMA_F16U(acc[i][2 * jp],     af[i], bf[jp][0], bf[jp][1]);
                    MMA_F16U(acc[i][2 * jp + 1], af[i], bf[jp][2], bf[jp][3]);
                }
        }
    };

    float bsqr[2][2];
#pragma unroll
    for (int i = 0; i < 2; ++i) {
        int r0 = bNp + wm + 16 * i + g;
        bsqr[i][0] = g_bsq[r0];
        bsqr[i][1] = g_bsq[r0 + 8];
    }

    auto epilogue = [&](int nt) {
        int bNn = nb0 + nt * 128;
        float msv[8][2];
#pragma unroll
        for (int j = 0; j < 8; ++j) {
            int c0 = bNn + wn + 8 * j + 2 * tg;
            msv[j][0] = g_msn[c0];
            msv[j][1] = g_msn[c0 + 1];
        }
        float rsum[2][2];
        rsum[0][0] = rsum[0][1] = rsum[1][0] = rsum[1][1] = 0.f;
#pragma unroll
        for (int i = 0; i < 2; ++i) {
            int r0 = bNp + wm + 16 * i + g;
            int r1 = r0 + 8;
#pragma unroll
            for (int j = 0; j < 8; ++j) {
                int c0 = bNn + wn + 8 * j + 2 * tg;
                __half h0 = __float2half_rn(__expf(msv[j][0] * (acc[i][j][0] - bsqr[i][0])));
                __half h1 = __float2half_rn(__expf(msv[j][1] * (acc[i][j][1] - bsqr[i][0])));
                __half h2 = __float2half_rn(__expf(msv[j][0] * (acc[i][j][2] - bsqr[i][1])));
                __half h3 = __float2half_rn(__expf(msv[j][1] * (acc[i][j][3] - bsqr[i][1])));
                *(__half2*)&g_SH[(size_t)r0 * NN + c0] = __halves2half2(h0, h1);
                *(__half2*)&g_SH[(size_t)r1 * NN + c0] = __halves2half2(h2, h3);
                rsum[i][0] += __half2float(h0) + __half2float(h1);
                rsum[i][1] += __half2float(h2) + __half2float(h3);
            }
        }
#pragma unroll
        for (int i = 0; i < 2; ++i)
#pragma unroll
            for (int d = 0; d < 2; ++d) {
                float s = rsum[i][d];
                s += __shfl_xor_sync(0xffffffffu, s, 1);
                s += __shfl_xor_sync(0xffffffffu, s, 2);
                if (tg == 0) red[nw][wm + 16 * i + 8 * d + g] = s;
            }
        __syncthreads();
        if (tid < 128)
            g_part[(size_t)(blockIdx.x * 2 + nt) * NP + bNp + tid] =
                red[0][tid] + red[1][tid];
    };

    auto zacc = [&]() {
#pragma unroll
        for (int i = 0; i < 2; ++i)
#pragma unroll
            for (int j = 0; j < 8; ++j)
#pragma unroll
                for (int r = 0; r < 4; ++r) acc[i][j][r] = 0.f;
    };

    // prologue: G0 = {Q0, Q1, M(n0,k0)->M0}, G1 = {M(n0,k1)->M1}
    load_q(0); load_q(1); load_m(0, 0, 0); CP_COMMIT();
    load_m(0, 1, 1); CP_COMMIT();

    // s0: (n0,k0) reads M0; refill -> M2 (untouched buffer)
    CP_WAIT(1); __syncthreads();
    load_m(1, 0, 2); CP_COMMIT();       // G2
    zacc();
    mma_step(QB0, MB[0]);
    // s1: (n0,k1) reads M1; refill -> M0 (s1's barrier orders s0's M0 reads first)
    CP_WAIT(1); __syncthreads();
    load_m(1, 1, 0); CP_COMMIT();       // G3
    mma_step(QB1, MB[1]);
    epilogue(0);
    // s2: (n1,k0) reads M2
    CP_WAIT(1); __syncthreads();
    zacc();
    mma_step(QB0, MB[2]);
    // s3: (n1,k1) reads M0
    CP_WAIT(0); __syncthreads();
    mma_step(QB1, MB[0]);
    epilogue(1);
}

// ---------------- rinv ----------------
__global__ void rinv_kernel() {
    int p = blockIdx.x * blockDim.x + threadIdx.x;
    float s = 0.f;
#pragma unroll
    for (int b = 0; b < NBLK; ++b) s += g_part[(size_t)b * NP + p];
    g_rinv[p] = 1.0f / s;
}

// ---------------- readout GEMM: fp16 m16n8k16 + LDSM, interleaved loads ----------
// out[v][p] = rinv[p] * sum_n MVh[v][n] * E^T[p][n]
#define OBK   64
#define ONKT  (NN / OBK)        // 128
#define OSTG  (2 * TSZ)         // 36864 B per stage
#define OSMEM (3 * OSTG)        // 110592 B

__global__ __launch_bounds__(256, 2) void out_gemm_kernel(float* __restrict__ out) {
    extern __shared__ __half Sh[];
    const int tid  = threadIdx.x;
    const int warp = tid >> 5;
    const int lane = tid & 31;
    const int bM = blockIdx.x * 128;   // v offset (x fastest -> 8 CTAs share E strip)
    const int bN = blockIdx.y * 128;   // p offset
    const int wm = (warp & 3) * 32;
    const int wn = (warp >> 2) * 64;
    const int g  = lane >> 2;
    const int tg = lane & 3;
    const uint32_t sbase = smem_u32(Sh);

    uint32_t aoff[2];
#pragma unroll
    for (int i = 0; i < 2; ++i)
        aoff[i] = (uint32_t)(wm + 16 * i + (lane & 15)) * RS + ((lane >> 4) & 1) * 16;
    uint32_t boff[4];
#pragma unroll
    for (int jp = 0; jp < 4; ++jp)
        boff[jp] = TSZ +
                   (uint32_t)(wn + 16 * jp + ((lane >> 4) & 1) * 8 + (lane & 7)) * RS +
                   ((lane >> 3) & 1) * 16;

    float acc[2][8][4];
#pragma unroll
    for (int i = 0; i < 2; ++i)
#pragma unroll
        for (int j = 0; j < 8; ++j)
#pragma unroll
            for (int r = 0; r < 4; ++r) acc[i][j][r] = 0.f;

    auto load_A = [&](int kt, int st) {
        uint32_t ab = sbase + st * OSTG;
#pragma unroll
        for (int s = 0; s < 4; ++s) {
            int id = tid + s * 256;
            int r = id >> 3, c = id & 7;
            cp16(ab + r * RS + c * 16, &g_MVh[(size_t)(bM + r) * NN + kt * OBK + c * 8]);
        }
    };
    auto load_B = [&](int kt, int st) {
        uint32_t bb = sbase + st * OSTG + TSZ;
#pragma unroll
        for (int s = 0; s < 4; ++s) {
            int id = tid + s * 256;
            int r = id >> 3, c = id & 7;
            cp16(bb + r * RS + c * 16, &g_SH[(size_t)(bN + r) * NN + kt * OBK + c * 8]);
        }
    };

    load_A(0, 0); load_B(0, 0); CP_COMMIT();
    load_A(1, 1); load_B(1, 1); CP_COMMIT();

    for (int kt = 0; kt < ONKT; ++kt) {
        if (kt + 1 < ONKT) CP_WAIT(1);
        else               CP_WAIT(0);
        __syncthreads();

        const uint32_t stb = sbase + (kt % 3) * OSTG;
        const bool pf = (kt + 2 < ONKT);
        const int pfs = (kt + 2) % 3;

#pragma unroll
        for (int ks = 0; ks < 4; ++ks) {       // 4 x k16
            const uint32_t kb = ks * 32;
            uint32_t af[2][4], bf[4][4];
            ldsm4(af[0], stb + aoff[0] + kb);
            ldsm4(af[1], stb + aoff[1] + kb);
#pragma unroll
            for (int jp = 0; jp < 4; ++jp)
                ldsm4(bf[jp], stb + boff[jp] + kb);
#pragma unroll
            for (int i = 0; i < 2; ++i)
#pragma unroll
                for (int jp = 0; jp < 4; ++jp) {
                    MMA_F16U(acc[i][2 * jp],     af[i], bf[jp][0], bf[jp][1]);
                    MMA_F16U(acc[i][2 * jp + 1], af[i], bf[jp][2], bf[jp][3]);
                }
            // slide next-stage loads under the MMA work (stage drained at kt-1)
            if (ks == 0 && pf) load_A(kt + 2, pfs);
            if (ks == 1 && pf) { load_B(kt + 2, pfs); CP_COMMIT(); }
        }
    }

    // epilogue: scale by rinv[p]
#pragma unroll
    for (int j = 0; j < 8; ++j) {
        int c = bN + wn + 8 * j + 2 * tg;
        float r0 = g_rinv[c];
        float r1 = g_rinv[c + 1];
#pragma unroll
        for (int i = 0; i < 2; ++i) {
            int rr = bM + wm + 16 * i + g;
            *(float2*)&out[(size_t)rr * NP + c] =
                make_float2(acc[i][j][0] * r0, acc[i][j][1] * r1);
            *(float2*)&out[(size_t)(rr + 8) * NP + c] =
                make_float2(acc[i][j][2] * r0, acc[i][j][3] * r1);
        }
    }
}

// ---------------- launch ----------------
extern "C" void kernel_launch(void* const* d_in, const int* in_sizes, int n_in,
                              void* d_out, int out_size) {
    const float* qk = (const float*)d_in[0];
    const float* qe = (const float*)d_in[1];
    const float* mk = (const float*)d_in[2];
    const float* ms = (const float*)d_in[3];
    const float* mv = (const float*)d_in[4];
    float* out = (float*)d_out;

    cudaFuncSetAttribute(sim_kernel, cudaFuncAttributeMaxDynamicSharedMemorySize, SSMEM);
    cudaFuncSetAttribute(out_gemm_kernel, cudaFuncAttributeMaxDynamicSharedMemorySize, OSMEM);

    prep_q_kernel<<<NP / 256, 256>>>(qk, qe);
    prep_m_kernel<<<NN / 256, 256>>>(mk, ms);
    prep_mv_kernel<<<(NV * NN / 4) / 256, 256>>>(mv);
    sim_kernel<<<dim3(NN / 256, NP / 128), 256, SSMEM>>>();
    rinv_kernel<<<NP / 256, 256>>>();
    out_gemm_kernel<<<dim3(NV / 128, NP / 128), 256, OSMEM>>>(out);
}

// round 14
// speedup vs baseline: 3.0357x; 1.2894x over previous
#include <cuda_runtime.h>
#include <cuda_fp16.h>
#include <cstdint>
#include <cstddef>

#define CKDIM 64
#define K2    128
#define NP    4096
#define NN    8192
#define NV    1024
#define NBLK  64

// ---------------- scratch ----------------
__device__ __half g_SH[(size_t)NP * NN];           // E^T[p][n] fp16 (67 MB, K-major)
__device__ __half g_QH[(size_t)NP * K2];           // [p][k] fp16 [2qk*qe; -qe]
__device__ __half g_MH[(size_t)NN * K2];           // [n][k] fp16 [mk; mk^2]
__device__ __half g_MVh[(size_t)NV * NN];          // fp16 mv (16 MB, K-major)
__device__ float g_bsq[NP];
__device__ float g_msn[NN];
__device__ float g_part[(size_t)NBLK * NP];
__device__ float g_rinv[NP];

__device__ __forceinline__ void cp16(uint32_t dst, const void* src) {
    asm volatile("cp.async.cg.shared.global [%0], [%1], 16;\n" :: "r"(dst), "l"(src));
}
__device__ __forceinline__ uint32_t smem_u32(const void* p) {
    return (uint32_t)__cvta_generic_to_shared(p);
}
__device__ __forceinline__ void ldsm4(uint32_t* r, uint32_t addr) {
    asm volatile("ldmatrix.sync.aligned.m8n8.x4.shared.b16 {%0,%1,%2,%3}, [%4];"
                 : "=r"(r[0]), "=r"(r[1]), "=r"(r[2]), "=r"(r[3]) : "r"(addr));
}
#define MMA_F16U(acc, a, b0, b1)                                                     \
    asm volatile(                                                                    \
        "mma.sync.aligned.m16n8k16.row.col.f32.f16.f16.f32 "                         \
        "{%0,%1,%2,%3}, {%4,%5,%6,%7}, {%8,%9}, {%0,%1,%2,%3};\n"                    \
        : "+f"((acc)[0]), "+f"((acc)[1]), "+f"((acc)[2]), "+f"((acc)[3])             \
        : "r"((a)[0]), "r"((a)[1]), "r"((a)[2]), "r"((a)[3]), "r"(b0), "r"(b1))
#define CP_COMMIT()  asm volatile("cp.async.commit_group;\n" ::)
#define CP_WAIT(N)   asm volatile("cp.async.wait_group %0;\n" :: "n"(N))

// row stride for all GEMM smem tiles: 64 fp16 data + 8 pad = 144 B
#define RS    144
#define TSZ   (128 * RS)      // 18432 B per operand tile

// ---------------- prep kernels (re-gridded: 32 rows x 8 chunk groups) ------------
__global__ void prep_q_kernel(const float* __restrict__ qk, const float* __restrict__ qe) {
    __shared__ float red[8][33];
    const int lane = threadIdx.x;          // p within block
    const int cg   = threadIdx.y;          // c chunk group
    const int p = blockIdx.x * 32 + lane;
    float bsq = 0.f;
    __align__(16) __half hq[8], he[8];
#pragma unroll
    for (int u = 0; u < 8; ++u) {
        int c = cg * 8 + u;
        float k = qk[c * NP + p];
        float e = qe[c * NP + p];
        hq[u] = __float2half_rn(2.f * k * e);
        he[u] = __float2half_rn(-e);
        bsq = fmaf(e * k, k, bsq);
    }
    *(uint4*)&g_QH[(size_t)p * K2 + cg * 8]      = *(uint4*)hq;
    *(uint4*)&g_QH[(size_t)p * K2 + 64 + cg * 8] = *(uint4*)he;
    red[cg][lane] = bsq;
    __syncthreads();
    if (cg == 0) {
        float s = bsq;
#pragma unroll
        for (int y = 1; y < 8; ++y) s += red[y][lane];
        g_bsq[p] = s;
    }
}

__global__ void prep_m_kernel(const float* __restrict__ mk, const float* __restrict__ ms) {
    const int lane = threadIdx.x;
    const int cg   = threadIdx.y;
    const int n = blockIdx.x * 32 + lane;
    __align__(16) __half hv[8], hv2[8];
#pragma unroll
    for (int u = 0; u < 8; ++u) {
        int c = cg * 8 + u;
        float v = mk[c * NN + n];
        hv[u]  = __float2half_rn(v);
        hv2[u] = __float2half_rn(v * v);
    }
    *(uint4*)&g_MH[(size_t)n * K2 + cg * 8]      = *(uint4*)hv;
    *(uint4*)&g_MH[(size_t)n * K2 + 64 + cg * 8] = *(uint4*)hv2;
    if (cg == 0) g_msn[n] = ms[n] * 0.125f;
}

__global__ void prep_mv_kernel(const float* __restrict__ mv) {
    size_t i = (size_t)blockIdx.x * blockDim.x + threadIdx.x;   // float4 index
    float4 v = ((const float4*)mv)[i];
    __half2 h01 = __floats2half2_rn(v.x, v.y);
    __half2 h23 = __floats2half2_rn(v.z, v.w);
    uint2 pk;
    pk.x = *(uint32_t*)&h01;
    pk.y = *(uint32_t*)&h23;
    ((uint2*)g_MVh)[i] = pk;
}

// ---------------- sim kernel: fp16 m16n8k16, 2 n-tiles per CTA, resident Q -------
// grid (32, 32): x = n-pair (256 n), y = p-tile (128 p).
// smem: Q[k0] | Q[k1] | M0 | M1 | M2 (ring)   (5 * TSZ = 92160 B)
#define SSMEM (5 * TSZ)

__global__ __launch_bounds__(256, 2) void sim_kernel() {
    extern __shared__ __half sh[];
    __shared__ float red[2][128];

    const int tid  = threadIdx.x;
    const int bNp  = blockIdx.y * 128;       // p offset
    const int nb0  = blockIdx.x * 256;       // first n tile
    const int warp = tid >> 5;
    const int lane = tid & 31;
    const int wm = (warp & 3) * 32;          // p warp tile
    const int nw = warp >> 2;
    const int wn = nw * 64;                  // n warp tile
    const int g  = lane >> 2;
    const int tg = lane & 3;
    const uint32_t sbase = smem_u32(sh);
    const uint32_t QB0 = sbase;
    const uint32_t QB1 = sbase + TSZ;
    const uint32_t MB[3] = {sbase + 2 * TSZ, sbase + 3 * TSZ, sbase + 4 * TSZ};

    uint32_t aoff[2];
#pragma unroll
    for (int i = 0; i < 2; ++i)
        aoff[i] = (uint32_t)(wm + 16 * i + (lane & 15)) * RS + ((lane >> 4) & 1) * 16;
    uint32_t boff[4];
#pragma unroll
    for (int jp = 0; jp < 4; ++jp)
        boff[jp] = (uint32_t)(wn + 16 * jp + ((lane >> 4) & 1) * 8 + (lane & 7)) * RS +
                   ((lane >> 3) & 1) * 16;

    float acc[2][8][4];

    auto load_q = [&](int kt) {
        uint32_t ab = sbase + kt * TSZ;
#pragma unroll
        for (int s = 0; s < 4; ++s) {
            int id = tid + s * 256;
            int r = id >> 3, c = id & 7;
            cp16(ab + r * RS + c * 16, &g_QH[(size_t)(bNp + r) * K2 + kt * 64 + c * 8]);
        }
    };
    auto load_m = [&](int nt, int kt, int buf) {
        uint32_t mb = MB[buf];
        int bNn = nb0 + nt * 128;
#pragma unroll
        for (int s = 0; s < 4; ++s) {
            int id = tid + s * 256;
            int r = id >> 3, c = id & 7;
            cp16(mb + r * RS + c * 16, &g_MH[(size_t)(bNn + r) * K2 + kt * 64 + c * 8]);
        }
    };
    auto mma_step = [&](uint32_t qb, uint32_t mb) {
#pragma unroll
        for (int ks = 0; ks < 4; ++ks) {
            const uint32_t kb = ks * 32;
            uint32_t af[2][4], bf[4][4];
            ldsm4(af[0], qb + aoff[0] + kb);
            ldsm4(af[1], qb + aoff[1] + kb);
            ldsm4(bf[0], mb + boff[0] + kb);
            ldsm4(bf[1], mb + boff[1] + kb);
            MMA_F16U(acc[0][0], af[0], bf[0][0], bf[0][1]);
            MMA_F16U(acc[0][1], af[0], bf[0][2], bf[0][3]);
            ldsm4(bf[2], mb + boff[2] + kb);
            MMA_F16U(acc[1][0], af[1], bf[0][0], bf[0][1]);
            MMA_F16U(acc[1][1], af[1], bf[0][2], bf[0][3]);
            ldsm4(bf[3], mb + boff[3] + kb);
            MMA_F16U(acc[0][2], af[0], bf[1][0], bf[1][1]);
            MMA_F16U(acc[0][3], af[0], bf[1][2], bf[1][3]);
            MMA_F16U(acc[1][2], af[1], bf[1][0], bf[1][1]);
            MMA_F16U(acc[1][3], af[1], bf[1][2], bf[1][3]);
#pragma unroll
            for (int i = 0; i < 2; ++i)
#pragma unroll
                for (int jp = 2; jp < 4; ++jp) {
                    MMA_F16U(acc[i][2 * jp],     af[i], bf[jp][0], bf[jp][1]);
                    MMA_F16U(acc[i][2 * jp + 1], af[i], bf[jp][2], bf[jp][3]);
                }
        }
    };

    float bsqr[2][2];
#pragma unroll
    for (int i = 0; i < 2; ++i) {
        int r0 = bNp + wm + 16 * i + g;
        bsqr[i][0] = g_bsq[r0];
        bsqr[i][1] = g_bsq[r0 + 8];
    }

    auto epilogue = [&](int nt) {
        int bNn = nb0 + nt * 128;
        float msv[8][2];
#pragma unroll
        for (int j = 0; j < 8; ++j) {
            int c0 = bNn + wn + 8 * j + 2 * tg;
            msv[j][0] = g_msn[c0];
            msv[j][1] = g_msn[c0 + 1];
        }
        float rsum[2][2];
        rsum[0][0] = rsum[0][1] = rsum[1][0] = rsum[1][1] = 0.f;
#pragma unroll
        for (int i = 0; i < 2; ++i) {
            int r0 = bNp + wm + 16 * i + g;
            int r1 = r0 + 8;
#pragma unroll
            for (int j = 0; j < 8; ++j) {
                int c0 = bNn + wn + 8 * j + 2 * tg;
                __half h0 = __float2half_rn(__expf(msv[j][0] * (acc[i][j][0] - bsqr[i][0])));
                __half h1 = __float2half_rn(__expf(msv[j][1] * (acc[i][j][1] - bsqr[i][0])));
                __half h2 = __float2half_rn(__expf(msv[j][0] * (acc[i][j][2] - bsqr[i][1])));
                __half h3 = __float2half_rn(__expf(msv[j][1] * (acc[i][j][3] - bsqr[i][1])));
                *(__half2*)&g_SH[(size_t)r0 * NN + c0] = __halves2half2(h0, h1);
                *(__half2*)&g_SH[(size_t)r1 * NN + c0] = __halves2half2(h2, h3);
                rsum[i][0] += __half2float(h0) + __half2float(h1);
                rsum[i][1] += __half2float(h2) + __half2float(h3);
            }
        }
#pragma unroll
        for (int i = 0; i < 2; ++i)
#pragma unroll
            for (int d = 0; d < 2; ++d) {
                float s = rsum[i][d];
                s += __shfl_xor_sync(0xffffffffu, s, 1);
                s += __shfl_xor_sync(0xffffffffu, s, 2);
                if (tg == 0) red[nw][wm + 16 * i + 8 * d + g] = s;
            }
        __syncthreads();
        if (tid < 128)
            g_part[(size_t)(blockIdx.x * 2 + nt) * NP + bNp + tid] =
                red[0][tid] + red[1][tid];
    };

    auto zacc = [&]() {
#pragma unroll
        for (int i = 0; i < 2; ++i)
#pragma unroll
            for (int j = 0; j < 8; ++j)
#pragma unroll
                for (int r = 0; r < 4; ++r) acc[i][j][r] = 0.f;
    };

    // prologue: G0 = {Q0, Q1, M(n0,k0)->M0}, G1 = {M(n0,k1)->M1}
    load_q(0); load_q(1); load_m(0, 0, 0); CP_COMMIT();
    load_m(0, 1, 1); CP_COMMIT();

    // s0: (n0,k0) reads M0; refill -> M2 (untouched buffer)
    CP_WAIT(1); __syncthreads();
    load_m(1, 0, 2); CP_COMMIT();       // G2
    zacc();
    mma_step(QB0, MB[0]);
    // s1: (n0,k1) reads M1; refill -> M0 (s1's barrier orders s0's M0 reads first)
    CP_WAIT(1); __syncthreads();
    load_m(1, 1, 0); CP_COMMIT();       // G3
    mma_step(QB1, MB[1]);
    epilogue(0);
    // s2: (n1,k0) reads M2
    CP_WAIT(1); __syncthreads();
    zacc();
    mma_step(QB0, MB[2]);
    // s3: (n1,k1) reads M0
    CP_WAIT(0); __syncthreads();
    mma_step(QB1, MB[0]);
    epilogue(1);
}

// ---------------- rinv (re-gridded) ----------------
__global__ void rinv_kernel() {
    __shared__ float red[8][33];
    const int lane = threadIdx.x;
    const int bg   = threadIdx.y;
    const int p = blockIdx.x * 32 + lane;
    float s = 0.f;
#pragma unroll
    for (int u = 0; u < 8; ++u)
        s += g_part[(size_t)(bg * 8 + u) * NP + p];
    red[bg][lane] = s;
    __syncthreads();
    if (bg == 0) {
#pragma unroll
        for (int y = 1; y < 8; ++y) s += red[y][lane];
        g_rinv[p] = 1.0f / s;
    }
}

// ---------------- readout GEMM: fp16 m16n8k16 + LDSM, interleaved loads ----------
// out[v][p] = rinv[p] * sum_n MVh[v][n] * E^T[p][n]
#define OBK   64
#define ONKT  (NN / OBK)        // 128
#define OSTG  (2 * TSZ)         // 36864 B per stage
#define OSMEM (3 * OSTG)        // 110592 B

__global__ __launch_bounds__(256, 2) void out_gemm_kernel(float* __restrict__ out) {
    extern __shared__ __half Sh[];
    const int tid  = threadIdx.x;
    const int warp = tid >> 5;
    const int lane = tid & 31;
    const int bM = blockIdx.x * 128;   // v offset (x fastest -> 8 CTAs share E strip)
    const int bN = blockIdx.y * 128;   // p offset
    const int wm = (warp & 3) * 32;
    const int wn = (warp >> 2) * 64;
    const int g  = lane >> 2;
    const int tg = lane & 3;
    const uint32_t sbase = smem_u32(Sh);

    uint32_t aoff[2];
#pragma unroll
    for (int i = 0; i < 2; ++i)
        aoff[i] = (uint32_t)(wm + 16 * i + (lane & 15)) * RS + ((lane >> 4) & 1) * 16;
    uint32_t boff[4];
#pragma unroll
    for (int jp = 0; jp < 4; ++jp)
        boff[jp] = TSZ +
                   (uint32_t)(wn + 16 * jp + ((lane >> 4) & 1) * 8 + (lane & 7)) * RS +
                   ((lane >> 3) & 1) * 16;

    float acc[2][8][4];
#pragma unroll
    for (int i = 0; i < 2; ++i)
#pragma unroll
        for (int j = 0; j < 8; ++j)
#pragma unroll
            for (int r = 0; r < 4; ++r) acc[i][j][r] = 0.f;

    auto load_A = [&](int kt, int st) {
        uint32_t ab = sbase + st * OSTG;
#pragma unroll
        for (int s = 0; s < 4; ++s) {
            int id = tid + s * 256;
            int r = id >> 3, c = id & 7;
            cp16(ab + r * RS + c * 16, &g_MVh[(size_t)(bM + r) * NN + kt * OBK + c * 8]);
        }
    };
    auto load_B = [&](int kt, int st) {
        uint32_t bb = sbase + st * OSTG + TSZ;
#pragma unroll
        for (int s = 0; s < 4; ++s) {
            int id = tid + s * 256;
            int r = id >> 3, c = id & 7;
            cp16(bb + r * RS + c * 16, &g_SH[(size_t)(bN + r) * NN + kt * OBK + c * 8]);
        }
    };

    load_A(0, 0); load_B(0, 0); CP_COMMIT();
    load_A(1, 1); load_B(1, 1); CP_COMMIT();

    for (int kt = 0; kt < ONKT; ++kt) {
        if (kt + 1 < ONKT) CP_WAIT(1);
        else               CP_WAIT(0);
        __syncthreads();

        const uint32_t stb = sbase + (kt % 3) * OSTG;
        const bool pf = (kt + 2 < ONKT);
        const int pfs = (kt + 2) % 3;

#pragma unroll
        for (int ks = 0; ks < 4; ++ks) {       // 4 x k16
            const uint32_t kb = ks * 32;
            uint32_t af[2][4], bf[4][4];
            ldsm4(af[0], stb + aoff[0] + kb);
            ldsm4(af[1], stb + aoff[1] + kb);
            ldsm4(bf[0], stb + boff[0] + kb);
            ldsm4(bf[1], stb + boff[1] + kb);
            MMA_F16U(acc[0][0], af[0], bf[0][0], bf[0][1]);
            MMA_F16U(acc[0][1], af[0], bf[0][2], bf[0][3]);
            ldsm4(bf[2], stb + boff[2] + kb);
            MMA_F16U(acc[1][0], af[1], bf[0][0], bf[0][1]);
            MMA_F16U(acc[1][1], af[1], bf[0][2], bf[0][3]);
            ldsm4(bf[3], stb + boff[3] + kb);
            MMA_F16U(acc[0][2], af[0], bf[1][0], bf[1][1]);
            MMA_F16U(acc[0][3], af[0], bf[1][2], bf[1][3]);
            MMA_F16U(acc[1][2], af[1], bf[1][0], bf[1][1]);
            MMA_F16U(acc[1][3], af[1], bf[1][2], bf[1][3]);
#pragma unroll
            for (int i = 0; i < 2; ++i)
#pragma unroll
                for (int jp = 2; jp < 4; ++jp) {
                    MMA_F16U(acc[i][2 * jp],     af[i], bf[jp][0], bf[jp][1]);
                    MMA_F16U(acc[i][2 * jp + 1], af[i], bf[jp][2], bf[jp][3]);
                }
            // slide next-stage loads under the MMA work (stage drained at kt-1)
            if (ks == 0 && pf) load_A(kt + 2, pfs);
            if (ks == 1 && pf) { load_B(kt + 2, pfs); CP_COMMIT(); }
        }
    }

    // epilogue: scale by rinv[p]
#pragma unroll
    for (int j = 0; j < 8; ++j) {
        int c = bN + wn + 8 * j + 2 * tg;
        float r0 = g_rinv[c];
        float r1 = g_rinv[c + 1];
#pragma unroll
        for (int i = 0; i < 2; ++i) {
            int rr = bM + wm + 16 * i + g;
            *(float2*)&out[(size_t)rr * NP + c] =
                make_float2(acc[i][j][0] * r0, acc[i][j][1] * r1);
            *(float2*)&out[(size_t)(rr + 8) * NP + c] =
                make_float2(acc[i][j][2] * r0, acc[i][j][3] * r1);
        }
    }
}

// ---------------- launch ----------------
extern "C" void kernel_launch(void* const* d_in, const int* in_sizes, int n_in,
                              void* d_out, int out_size) {
    const float* qk = (const float*)d_in[0];
    const float* qe = (const float*)d_in[1];
    const float* mk = (const float*)d_in[2];
    const float* ms = (const float*)d_in[3];
    const float* mv = (const float*)d_in[4];
    float* out = (float*)d_out;

    cudaFuncSetAttribute(sim_kernel, cudaFuncAttributeMaxDynamicSharedMemorySize, SSMEM);
    cudaFuncSetAttribute(out_gemm_kernel, cudaFuncAttributeMaxDynamicSharedMemorySize, OSMEM);

    prep_q_kernel<<<NP / 32, dim3(32, 8)>>>(qk, qe);
    prep_m_kernel<<<NN / 32, dim3(32, 8)>>>(mk, ms);
    prep_mv_kernel<<<(NV * NN / 4) / 256, 256>>>(mv);
    sim_kernel<<<dim3(NN / 256, NP / 128), 256, SSMEM>>>();
    rinv_kernel<<<NP / 32, dim3(32, 8)>>>();
    out_gemm_kernel<<<dim3(NV / 128, NP / 128), 256, OSMEM>>>(out);
}

// round 15
// speedup vs baseline: 3.0880x; 1.0172x over previous
#include <cuda_runtime.h>
#include <cuda_fp16.h>
#include <cstdint>
#include <cstddef>

#define CKDIM 64
#define K2    128
#define NP    4096
#define NN    8192
#define NV    1024
#define NBLK  64

// ---------------- scratch ----------------
__device__ __half g_SH[(size_t)NP * NN];           // E^T[p][n] fp16 (67 MB, K-major)
__device__ __half g_QH[(size_t)NP * K2];           // [p][k] fp16 [2qk*qe; -qe]
__device__ __half g_MH[(size_t)NN * K2];           // [n][k] fp16 [mk; mk^2]
__device__ __half g_MVh[(size_t)NV * NN];          // fp16 mv (16 MB, K-major)
__device__ float g_bsq[NP];
__device__ float g_msn[NN];
__device__ float g_part[(size_t)NBLK * NP];
__device__ float g_rinv[NP];

__device__ __forceinline__ void cp16(uint32_t dst, const void* src) {
    asm volatile("cp.async.cg.shared.global [%0], [%1], 16;\n" :: "r"(dst), "l"(src));
}
__device__ __forceinline__ uint32_t smem_u32(const void* p) {
    return (uint32_t)__cvta_generic_to_shared(p);
}
__device__ __forceinline__ void ldsm4(uint32_t* r, uint32_t addr) {
    asm volatile("ldmatrix.sync.aligned.m8n8.x4.shared.b16 {%0,%1,%2,%3}, [%4];"
                 : "=r"(r[0]), "=r"(r[1]), "=r"(r[2]), "=r"(r[3]) : "r"(addr));
}
#define MMA_F16U(acc, a, b0, b1)                                                     \
    asm volatile(                                                                    \
        "mma.sync.aligned.m16n8k16.row.col.f32.f16.f16.f32 "                         \
        "{%0,%1,%2,%3}, {%4,%5,%6,%7}, {%8,%9}, {%0,%1,%2,%3};\n"                    \
        : "+f"((acc)[0]), "+f"((acc)[1]), "+f"((acc)[2]), "+f"((acc)[3])             \
        : "r"((a)[0]), "r"((a)[1]), "r"((a)[2]), "r"((a)[3]), "r"(b0), "r"(b1))
#define CP_COMMIT()  asm volatile("cp.async.commit_group;\n" ::)
#define CP_WAIT(N)   asm volatile("cp.async.wait_group %0;\n" :: "n"(N))

// row stride for all GEMM smem tiles: 64 fp16 data + 8 pad = 144 B
#define RS    144
#define TSZ   (128 * RS)      // 18432 B per operand tile

// ---------------- prep kernels (32 rows x 8 chunk groups) ------------
__global__ void prep_q_kernel(const float* __restrict__ qk, const float* __restrict__ qe) {
    __shared__ float red[8][33];
    const int lane = threadIdx.x;
    const int cg   = threadIdx.y;
    const int p = blockIdx.x * 32 + lane;
    float bsq = 0.f;
    __align__(16) __half hq[8], he[8];
#pragma unroll
    for (int u = 0; u < 8; ++u) {
        int c = cg * 8 + u;
        float k = qk[c * NP + p];
        float e = qe[c * NP + p];
        hq[u] = __float2half_rn(2.f * k * e);
        he[u] = __float2half_rn(-e);
        bsq = fmaf(e * k, k, bsq);
    }
    *(uint4*)&g_QH[(size_t)p * K2 + cg * 8]      = *(uint4*)hq;
    *(uint4*)&g_QH[(size_t)p * K2 + 64 + cg * 8] = *(uint4*)he;
    red[cg][lane] = bsq;
    __syncthreads();
    if (cg == 0) {
        float s = bsq;
#pragma unroll
        for (int y = 1; y < 8; ++y) s += red[y][lane];
        g_bsq[p] = s;
    }
}

__global__ void prep_m_kernel(const float* __restrict__ mk, const float* __restrict__ ms) {
    const int lane = threadIdx.x;
    const int cg   = threadIdx.y;
    const int n = blockIdx.x * 32 + lane;
    __align__(16) __half hv[8], hv2[8];
#pragma unroll
    for (int u = 0; u < 8; ++u) {
        int c = cg * 8 + u;
        float v = mk[c * NN + n];
        hv[u]  = __float2half_rn(v);
        hv2[u] = __float2half_rn(v * v);
    }
    *(uint4*)&g_MH[(size_t)n * K2 + cg * 8]      = *(uint4*)hv;
    *(uint4*)&g_MH[(size_t)n * K2 + 64 + cg * 8] = *(uint4*)hv2;
    if (cg == 0) g_msn[n] = ms[n] * 0.125f;
}

__global__ void prep_mv_kernel(const float* __restrict__ mv) {
    size_t i = (size_t)blockIdx.x * blockDim.x + threadIdx.x;   // float4 index
    float4 v = ((const float4*)mv)[i];
    __half2 h01 = __floats2half2_rn(v.x, v.y);
    __half2 h23 = __floats2half2_rn(v.z, v.w);
    uint2 pk;
    pk.x = *(uint32_t*)&h01;
    pk.y = *(uint32_t*)&h23;
    ((uint2*)g_MVh)[i] = pk;
}

// ---------------- sim kernel: fp16 m16n8k16, 2 n-tiles per CTA, resident Q -------
// grid (32, 32): x = n-pair (256 n), y = p-tile (128 p).
// smem: Q[k0] | Q[k1] | M0 | M1 | M2 (ring)   (5 * TSZ = 92160 B)
#define SSMEM (5 * TSZ)

__global__ __launch_bounds__(256, 2) void sim_kernel() {
    extern __shared__ __half sh[];
    __shared__ float red[2][128];

    const int tid  = threadIdx.x;
    const int bNp  = blockIdx.y * 128;       // p offset
    const int nb0  = blockIdx.x * 256;       // first n tile
    const int warp = tid >> 5;
    const int lane = tid & 31;
    const int wm = (warp & 3) * 32;          // p warp tile
    const int nw = warp >> 2;
    const int wn = nw * 64;                  // n warp tile
    const int g  = lane >> 2;
    const int tg = lane & 3;
    const uint32_t sbase = smem_u32(sh);
    const uint32_t QB0 = sbase;
    const uint32_t QB1 = sbase + TSZ;
    const uint32_t MB[3] = {sbase + 2 * TSZ, sbase + 3 * TSZ, sbase + 4 * TSZ};

    uint32_t aoff[2];
#pragma unroll
    for (int i = 0; i < 2; ++i)
        aoff[i] = (uint32_t)(wm + 16 * i + (lane & 15)) * RS + ((lane >> 4) & 1) * 16;
    uint32_t boff[4];
#pragma unroll
    for (int jp = 0; jp < 4; ++jp)
        boff[jp] = (uint32_t)(wn + 16 * jp + ((lane >> 4) & 1) * 8 + (lane & 7)) * RS +
                   ((lane >> 3) & 1) * 16;

    float acc[2][8][4];

    auto load_q = [&](int kt) {
        uint32_t ab = sbase + kt * TSZ;
#pragma unroll
        for (int s = 0; s < 4; ++s) {
            int id = tid + s * 256;
            int r = id >> 3, c = id & 7;
            cp16(ab + r * RS + c * 16, &g_QH[(size_t)(bNp + r) * K2 + kt * 64 + c * 8]);
        }
    };
    auto load_m = [&](int nt, int kt, int buf) {
        uint32_t mb = MB[buf];
        int bNn = nb0 + nt * 128;
#pragma unroll
        for (int s = 0; s < 4; ++s) {
            int id = tid + s * 256;
            int r = id >> 3, c = id & 7;
            cp16(mb + r * RS + c * 16, &g_MH[(size_t)(bNn + r) * K2 + kt * 64 + c * 8]);
        }
    };
    auto mma_step = [&](uint32_t qb, uint32_t mb) {
#pragma unroll
        for (int ks = 0; ks < 4; ++ks) {
            const uint32_t kb = ks * 32;
            uint32_t af[2][4], bf[4][4];
            ldsm4(af[0], qb + aoff[0] + kb);
            ldsm4(af[1], qb + aoff[1] + kb);
            ldsm4(bf[0], mb + boff[0] + kb);
            ldsm4(bf[1], mb + boff[1] + kb);
            MMA_F16U(acc[0][0], af[0], bf[0][0], bf[0][1]);
            MMA_F16U(acc[0][1], af[0], bf[0][2], bf[0][3]);
            ldsm4(bf[2], mb + boff[2] + kb);
            MMA_F16U(acc[1][0], af[1], bf[0][0], bf[0][1]);
            MMA_F16U(acc[1][1], af[1], bf[0][2], bf[0][3]);
            ldsm4(bf[3], mb + boff[3] + kb);
            MMA_F16U(acc[0][2], af[0], bf[1][0], bf[1][1]);
            MMA_F16U(acc[0][3], af[0], bf[1][2], bf[1][3]);
            MMA_F16U(acc[1][2], af[1], bf[1][0], bf[1][1]);
            MMA_F16U(acc[1][3], af[1], bf[1][2], bf[1][3]);
#pragma unroll
            for (int i = 0; i < 2; ++i)
#pragma unroll
                for (int jp = 2; jp < 4; ++jp) {
                    MMA_F16U(acc[i][2 * jp],     af[i], bf[jp][0], bf[jp][1]);
                    MMA_F16U(acc[i][2 * jp + 1], af[i], bf[jp][2], bf[jp][3]);
                }
        }
    };

    float bsqr[2][2];
#pragma unroll
    for (int i = 0; i < 2; ++i) {
        int r0 = bNp + wm + 16 * i + g;
        bsqr[i][0] = g_bsq[r0];
        bsqr[i][1] = g_bsq[r0 + 8];
    }

    auto epilogue = [&](int nt) {
        int bNn = nb0 + nt * 128;
        float msv[8][2];
#pragma unroll
        for (int j = 0; j < 8; ++j) {
            int c0 = bNn + wn + 8 * j + 2 * tg;
            msv[j][0] = g_msn[c0];
            msv[j][1] = g_msn[c0 + 1];
        }
        float rsum[2][2];
        rsum[0][0] = rsum[0][1] = rsum[1][0] = rsum[1][1] = 0.f;
#pragma unroll
        for (int i = 0; i < 2; ++i) {
            int r0 = bNp + wm + 16 * i + g;
            int r1 = r0 + 8;
#pragma unroll
            for (int j = 0; j < 8; ++j) {
                int c0 = bNn + wn + 8 * j + 2 * tg;
                __half h0 = __float2half_rn(__expf(msv[j][0] * (acc[i][j][0] - bsqr[i][0])));
                __half h1 = __float2half_rn(__expf(msv[j][1] * (acc[i][j][1] - bsqr[i][0])));
                __half h2 = __float2half_rn(__expf(msv[j][0] * (acc[i][j][2] - bsqr[i][1])));
                __half h3 = __float2half_rn(__expf(msv[j][1] * (acc[i][j][3] - bsqr[i][1])));
                *(__half2*)&g_SH[(size_t)r0 * NN + c0] = __halves2half2(h0, h1);
                *(__half2*)&g_SH[(size_t)r1 * NN + c0] = __halves2half2(h2, h3);
                rsum[i][0] += __half2float(h0) + __half2float(h1);
                rsum[i][1] += __half2float(h2) + __half2float(h3);
            }
        }
#pragma unroll
        for (int i = 0; i < 2; ++i)
#pragma unroll
            for (int d = 0; d < 2; ++d) {
                float s = rsum[i][d];
                s += __shfl_xor_sync(0xffffffffu, s, 1);
                s += __shfl_xor_sync(0xffffffffu, s, 2);
                if (tg == 0) red[nw][wm + 16 * i + 8 * d + g] = s;
            }
        __syncthreads();
        if (tid < 128)
            g_part[(size_t)(blockIdx.x * 2 + nt) * NP + bNp + tid] =
                red[0][tid] + red[1][tid];
    };

    auto zacc = [&]() {
#pragma unroll
        for (int i = 0; i < 2; ++i)
#pragma unroll
            for (int j = 0; j < 8; ++j)
#pragma unroll
                for (int r = 0; r < 4; ++r) acc[i][j][r] = 0.f;
    };

    // prologue: G0 = {Q0, Q1, M(n0,k0)->M0}, G1 = {M(n0,k1)->M1}
    load_q(0); load_q(1); load_m(0, 0, 0); CP_COMMIT();
    load_m(0, 1, 1); CP_COMMIT();

    // s0: (n0,k0) reads M0; refill -> M2 (untouched buffer)
    CP_WAIT(1); __syncthreads();
    load_m(1, 0, 2); CP_COMMIT();       // G2
    zacc();
    mma_step(QB0, MB[0]);
    // s1: (n0,k1) reads M1; refill -> M0 (s1's barrier orders s0's M0 reads first)
    CP_WAIT(1); __syncthreads();
    load_m(1, 1, 0); CP_COMMIT();       // G3
    mma_step(QB1, MB[1]);
    epilogue(0);
    // s2: (n1,k0) reads M2
    CP_WAIT(1); __syncthreads();
    zacc();
    mma_step(QB0, MB[2]);
    // s3: (n1,k1) reads M0
    CP_WAIT(0); __syncthreads();
    mma_step(QB1, MB[0]);
    epilogue(1);
}

// ---------------- rinv ----------------
__global__ void rinv_kernel() {
    __shared__ float red[8][33];
    const int lane = threadIdx.x;
    const int bg   = threadIdx.y;
    const int p = blockIdx.x * 32 + lane;
    float s = 0.f;
#pragma unroll
    for (int u = 0; u < 8; ++u)
        s += g_part[(size_t)(bg * 8 + u) * NP + p];
    red[bg][lane] = s;
    __syncthreads();
    if (bg == 0) {
#pragma unroll
        for (int y = 1; y < 8; ++y) s += red[y][lane];
        g_rinv[p] = 1.0f / s;
    }
}

// ---------------- readout GEMM: fp16 m16n8k16 + LDSM, 4 warps x 64x64 tiles ------
// out[v][p] = rinv[p] * sum_n MVh[v][n] * E^T[p][n]
// CTA 128x128, 128 threads (warp grid 2x2), BK=64, 3-stage cp.async ring.
#define OBK   64
#define ONKT  (NN / OBK)        // 128
#define OSTG  (2 * TSZ)         // 36864 B per stage
#define OSMEM (3 * OSTG)        // 110592 B

__global__ __launch_bounds__(128, 2) void out_gemm_kernel(float* __restrict__ out) {
    extern __shared__ __half Sh[];
    const int tid  = threadIdx.x;
    const int warp = tid >> 5;
    const int lane = tid & 31;
    const int bM = blockIdx.x * 128;   // v offset (x fastest -> 8 CTAs share E strip)
    const int bN = blockIdx.y * 128;   // p offset
    const int wm = (warp & 1) * 64;    // v warp tile (64)
    const int wn = (warp >> 1) * 64;   // p warp tile (64)
    const int g  = lane >> 2;
    const int tg = lane & 3;
    const uint32_t sbase = smem_u32(Sh);

    uint32_t aoff[4];
#pragma unroll
    for (int i = 0; i < 4; ++i)
        aoff[i] = (uint32_t)(wm + 16 * i + (lane & 15)) * RS + ((lane >> 4) & 1) * 16;
    uint32_t boff[4];
#pragma unroll
    for (int jp = 0; jp < 4; ++jp)
        boff[jp] = TSZ +
                   (uint32_t)(wn + 16 * jp + ((lane >> 4) & 1) * 8 + (lane & 7)) * RS +
                   ((lane >> 3) & 1) * 16;

    float acc[4][8][4];
#pragma unroll
    for (int i = 0; i < 4; ++i)
#pragma unroll
        for (int j = 0; j < 8; ++j)
#pragma unroll
            for (int r = 0; r < 4; ++r) acc[i][j][r] = 0.f;

    auto load_A = [&](int kt, int st) {
        uint32_t ab = sbase + st * OSTG;
#pragma unroll
        for (int s = 0; s < 8; ++s) {          // A: 1024 16B chunks / 128 threads
            int id = tid + s * 128;
            int r = id >> 3, c = id & 7;
            cp16(ab + r * RS + c * 16, &g_MVh[(size_t)(bM + r) * NN + kt * OBK + c * 8]);
        }
    };
    auto load_B = [&](int kt, int st) {
        uint32_t bb = sbase + st * OSTG + TSZ;
#pragma unroll
        for (int s = 0; s < 8; ++s) {
            int id = tid + s * 128;
            int r = id >> 3, c = id & 7;
            cp16(bb + r * RS + c * 16, &g_SH[(size_t)(bN + r) * NN + kt * OBK + c * 8]);
        }
    };

    load_A(0, 0); load_B(0, 0); CP_COMMIT();
    load_A(1, 1); load_B(1, 1); CP_COMMIT();

    for (int kt = 0; kt < ONKT; ++kt) {
        if (kt + 1 < ONKT) CP_WAIT(1);
        else               CP_WAIT(0);
        __syncthreads();

        const uint32_t stb = sbase + (kt % 3) * OSTG;
        const bool pf = (kt + 2 < ONKT);
        const int pfs = (kt + 2) % 3;

#pragma unroll
        for (int ks = 0; ks < 4; ++ks) {       // 4 x k16
            const uint32_t kb = ks * 32;
            uint32_t af[4][4], bf[4][4];
            ldsm4(af[0], stb + aoff[0] + kb);
            ldsm4(af[1], stb + aoff[1] + kb);
            ldsm4(af[2], stb + aoff[2] + kb);
            ldsm4(af[3], stb + aoff[3] + kb);
            ldsm4(bf[0], stb + boff[0] + kb);
            ldsm4(bf[1], stb + boff[1] + kb);
            MMA_F16U(acc[0][0], af[0], bf[0][0], bf[0][1]);
            MMA_F16U(acc[0][1], af[0], bf[0][2], bf[0][3]);
            MMA_F16U(acc[1][0], af[1], bf[0][0], bf[0][1]);
            MMA_F16U(acc[1][1], af[1], bf[0][2], bf[0][3]);
            ldsm4(bf[2], stb + boff[2] + kb);
            MMA_F16U(acc[2][0], af[2], bf[0][0], bf[0][1]);
            MMA_F16U(acc[2][1], af[2], bf[0][2], bf[0][3]);
            MMA_F16U(acc[3][0], af[3], bf[0][0], bf[0][1]);
            MMA_F16U(acc[3][1], af[3], bf[0][2], bf[0][3]);
            ldsm4(bf[3], stb + boff[3] + kb);
#pragma unroll
            for (int i = 0; i < 4; ++i) {
                MMA_F16U(acc[i][2], af[i], bf[1][0], bf[1][1]);
                MMA_F16U(acc[i][3], af[i], bf[1][2], bf[1][3]);
            }
#pragma unroll
            for (int i = 0; i < 4; ++i)
#pragma unroll
                for (int jp = 2; jp < 4; ++jp) {
                    MMA_F16U(acc[i][2 * jp],     af[i], bf[jp][0], bf[jp][1]);
                    MMA_F16U(acc[i][2 * jp + 1], af[i], bf[jp][2], bf[jp][3]);
                }
            // slide next-stage loads under the MMA work (stage drained at kt-1)
            if (ks == 0 && pf) load_A(kt + 2, pfs);
            if (ks == 1 && pf) { load_B(kt + 2, pfs); CP_COMMIT(); }
        }
    }

    // epilogue: scale by rinv[p]
#pragma unroll
    for (int j = 0; j < 8; ++j) {
        int c = bN + wn + 8 * j + 2 * tg;
        float r0 = g_rinv[c];
        float r1 = g_rinv[c + 1];
#pragma unroll
        for (int i = 0; i < 4; ++i) {
            int rr = bM + wm + 16 * i + g;
            *(float2*)&out[(size_t)rr * NP + c] =
                make_float2(acc[i][j][0] * r0, acc[i][j][1] * r1);
            *(float2*)&out[(size_t)(rr + 8) * NP + c] =
                make_float2(acc[i][j][2] * r0, acc[i][j][3] * r1);
        }
    }
}

// ---------------- launch ----------------
extern "C" void kernel_launch(void* const* d_in, const int* in_sizes, int n_in,
                              void* d_out, int out_size) {
    const float* qk = (const float*)d_in[0];
    const float* qe = (const float*)d_in[1];
    const float* mk = (const float*)d_in[2];
    const float* ms = (const float*)d_in[3];
    const float* mv = (const float*)d_in[4];
    float* out = (float*)d_out;

    cudaFuncSetAttribute(sim_kernel, cudaFuncAttributeMaxDynamicSharedMemorySize, SSMEM);
    cudaFuncSetAttribute(out_gemm_kernel, cudaFuncAttributeMaxDynamicSharedMemorySize, OSMEM);

    prep_q_kernel<<<NP / 32, dim3(32, 8)>>>(qk, qe);
    prep_m_kernel<<<NN / 32, dim3(32, 8)>>>(mk, ms);
    prep_mv_kernel<<<(NV * NN / 4) / 256, 256>>>(mv);
    sim_kernel<<<dim3(NN / 256, NP / 128), 256, SSMEM>>>();
    rinv_kernel<<<NP / 32, dim3(32, 8)>>>();
    out_gemm_kernel<<<dim3(NV / 128, NP / 128), 128, OSMEM>>>(out);
}

// round 16
// speedup vs baseline: 3.1146x; 1.0086x over previous
#include <cuda_runtime.h>
#include <cuda_fp16.h>
#include <cstdint>
#include <cstddef>

#define CKDIM 64
#define K2    128
#define NP    4096
#define NN    8192
#define NV    1024
#define NBLK  64

// ---------------- scratch ----------------
__device__ __half g_SH[(size_t)NP * NN];           // E^T[p][n] fp16 (67 MB, L2-resident)
__device__ __half g_QH[(size_t)NP * K2];           // [p][k] fp16 [2qk*qe; -qe]
__device__ __half g_MH[(size_t)NN * K2];           // [n][k] fp16 [mk; mk^2]
__device__ __half g_MVh[(size_t)NV * NN];          // fp16 mv (16 MB, K-major)
__device__ float g_bsq[NP];
__device__ float g_msn[NN];
__device__ float g_part[(size_t)NBLK * NP];
__device__ float g_rinv[NP];

__device__ __forceinline__ void cp16(uint32_t dst, const void* src) {
    asm volatile("cp.async.cg.shared.global [%0], [%1], 16;\n" :: "r"(dst), "l"(src));
}
__device__ __forceinline__ uint32_t smem_u32(const void* p) {
    return (uint32_t)__cvta_generic_to_shared(p);
}
__device__ __forceinline__ void ldsm4(uint32_t* r, uint32_t addr) {
    asm volatile("ldmatrix.sync.aligned.m8n8.x4.shared.b16 {%0,%1,%2,%3}, [%4];"
                 : "=r"(r[0]), "=r"(r[1]), "=r"(r[2]), "=r"(r[3]) : "r"(addr));
}
#define MMA_F16U(acc, a, b0, b1)                                                     \
    asm volatile(                                                                    \
        "mma.sync.aligned.m16n8k16.row.col.f32.f16.f16.f32 "                         \
        "{%0,%1,%2,%3}, {%4,%5,%6,%7}, {%8,%9}, {%0,%1,%2,%3};\n"                    \
        : "+f"((acc)[0]), "+f"((acc)[1]), "+f"((acc)[2]), "+f"((acc)[3])             \
        : "r"((a)[0]), "r"((a)[1]), "r"((a)[2]), "r"((a)[3]), "r"(b0), "r"(b1))
#define CP_COMMIT()  asm volatile("cp.async.commit_group;\n" ::)
#define CP_WAIT(N)   asm volatile("cp.async.wait_group %0;\n" :: "n"(N))

// row stride for all GEMM smem tiles: 64 fp16 data + 8 pad = 144 B
#define RS    144
#define TSZ   (128 * RS)      // 18432 B per operand tile

// ---------------- prep kernels (32 rows x 8 chunk groups) ------------
__global__ void prep_q_kernel(const float* __restrict__ qk, const float* __restrict__ qe) {
    __shared__ float red[8][33];
    const int lane = threadIdx.x;
    const int cg   = threadIdx.y;
    const int p = blockIdx.x * 32 + lane;
    float bsq = 0.f;
    __align__(16) __half hq[8], he[8];
#pragma unroll
    for (int u = 0; u < 8; ++u) {
        int c = cg * 8 + u;
        float k = qk[c * NP + p];
        float e = qe[c * NP + p];
        hq[u] = __float2half_rn(2.f * k * e);
        he[u] = __float2half_rn(-e);
        bsq = fmaf(e * k, k, bsq);
    }
    *(uint4*)&g_QH[(size_t)p * K2 + cg * 8]      = *(uint4*)hq;
    *(uint4*)&g_QH[(size_t)p * K2 + 64 + cg * 8] = *(uint4*)he;
    red[cg][lane] = bsq;
    __syncthreads();
    if (cg == 0) {
        float s = bsq;
#pragma unroll
        for (int y = 1; y < 8; ++y) s += red[y][lane];
        g_bsq[p] = s;
    }
}

__global__ void prep_m_kernel(const float* __restrict__ mk, const float* __restrict__ ms) {
    const int lane = threadIdx.x;
    const int cg   = threadIdx.y;
    const int n = blockIdx.x * 32 + lane;
    __align__(16) __half hv[8], hv2[8];
#pragma unroll
    for (int u = 0; u < 8; ++u) {
        int c = cg * 8 + u;
        float v = mk[c * NN + n];
        hv[u]  = __float2half_rn(v);
        hv2[u] = __float2half_rn(v * v);
    }
    *(uint4*)&g_MH[(size_t)n * K2 + cg * 8]      = *(uint4*)hv;
    *(uint4*)&g_MH[(size_t)n * K2 + 64 + cg * 8] = *(uint4*)hv2;
    if (cg == 0) g_msn[n] = ms[n] * 0.125f;
}

__global__ void prep_mv_kernel(const float* __restrict__ mv) {
    size_t i = (size_t)blockIdx.x * blockDim.x + threadIdx.x;   // float4 index
    float4 v = ((const float4*)mv)[i];
    __half2 h01 = __floats2half2_rn(v.x, v.y);
    __half2 h23 = __floats2half2_rn(v.z, v.w);
    uint2 pk;
    pk.x = *(uint32_t*)&h01;
    pk.y = *(uint32_t*)&h23;
    ((uint2*)g_MVh)[i] = pk;
}

// ---------------- sim kernel: fp16 m16n8k16, 2 n-tiles per CTA, resident Q -------
// grid (32, 32): x = n-pair (256 n), y = p-tile (128 p).
// smem: Q[k0] | Q[k1] | M0 | M1 | M2   (5 * TSZ = 92160 B)
// M1 is dead after step s1 (never refilled) -> reused as E-store staging buffer.
#define SSMEM (5 * TSZ)

__global__ __launch_bounds__(256, 2) void sim_kernel() {
    extern __shared__ __half sh[];
    __shared__ float red[2][128];

    const int tid  = threadIdx.x;
    const int bNp  = blockIdx.y * 128;       // p offset
    const int nb0  = blockIdx.x * 256;       // first n tile
    const int warp = tid >> 5;
    const int lane = tid & 31;
    const int wm = (warp & 3) * 32;          // p warp tile
    const int nw = warp >> 2;
    const int wn = nw * 64;                  // n warp tile
    const int g  = lane >> 2;
    const int tg = lane & 3;
    const uint32_t sbase = smem_u32(sh);
    const uint32_t QB0 = sbase;
    const uint32_t QB1 = sbase + TSZ;
    const uint32_t MB[3] = {sbase + 2 * TSZ, sbase + 3 * TSZ, sbase + 4 * TSZ};
    char* stg = (char*)sh + 3 * TSZ;         // generic pointer to M1 (staging)

    uint32_t aoff[2];
#pragma unroll
    for (int i = 0; i < 2; ++i)
        aoff[i] = (uint32_t)(wm + 16 * i + (lane & 15)) * RS + ((lane >> 4) & 1) * 16;
    uint32_t boff[4];
#pragma unroll
    for (int jp = 0; jp < 4; ++jp)
        boff[jp] = (uint32_t)(wn + 16 * jp + ((lane >> 4) & 1) * 8 + (lane & 7)) * RS +
                   ((lane >> 3) & 1) * 16;

    float acc[2][8][4];

    auto load_q = [&](int kt) {
        uint32_t ab = sbase + kt * TSZ;
#pragma unroll
        for (int s = 0; s < 4; ++s) {
            int id = tid + s * 256;
            int r = id >> 3, c = id & 7;
            cp16(ab + r * RS + c * 16, &g_QH[(size_t)(bNp + r) * K2 + kt * 64 + c * 8]);
        }
    };
    auto load_m = [&](int nt, int kt, int buf) {
        uint32_t mb = MB[buf];
        int bNn = nb0 + nt * 128;
#pragma unroll
        for (int s = 0; s < 4; ++s) {
            int id = tid + s * 256;
            int r = id >> 3, c = id & 7;
            cp16(mb + r * RS + c * 16, &g_MH[(size_t)(bNn + r) * K2 + kt * 64 + c * 8]);
        }
    };
    auto mma_step = [&](uint32_t qb, uint32_t mb) {
#pragma unroll
        for (int ks = 0; ks < 4; ++ks) {
            const uint32_t kb = ks * 32;
            uint32_t af[2][4], bf[4][4];
            ldsm4(af[0], qb + aoff[0] + kb);
            ldsm4(af[1], qb + aoff[1] + kb);
            ldsm4(bf[0], mb + boff[0] + kb);
            ldsm4(bf[1], mb + boff[1] + kb);
            MMA_F16U(acc[0][0], af[0], bf[0][0], bf[0][1]);
            MMA_F16U(acc[0][1], af[0], bf[0][2], bf[0][3]);
            ldsm4(bf[2], mb + boff[2] + kb);
            MMA_F16U(acc[1][0], af[1], bf[0][0], bf[0][1]);
            MMA_F16U(acc[1][1], af[1], bf[0][2], bf[0][3]);
            ldsm4(bf[3], mb + boff[3] + kb);
            MMA_F16U(acc[0][2], af[0], bf[1][0], bf[1][1]);
            MMA_F16U(acc[0][3], af[0], bf[1][2], bf[1][3]);
            MMA_F16U(acc[1][2], af[1], bf[1][0], bf[1][1]);
            MMA_F16U(acc[1][3], af[1], bf[1][2], bf[1][3]);
#pragma unroll
            for (int i = 0; i < 2; ++i)
#pragma unroll
                for (int jp = 2; jp < 4; ++jp) {
                    MMA_F16U(acc[i][2 * jp],     af[i], bf[jp][0], bf[jp][1]);
                    MMA_F16U(acc[i][2 * jp + 1], af[i], bf[jp][2], bf[jp][3]);
                }
        }
    };

    float bsqr[2][2];
#pragma unroll
    for (int i = 0; i < 2; ++i) {
        int r0 = bNp + wm + 16 * i + g;
        bsqr[i][0] = g_bsq[r0];
        bsqr[i][1] = g_bsq[r0 + 8];
    }

    // epilogue: stage E fragments into M1 (conflict-free), copy out coalesced.
    auto epilogue = [&](int nt) {
        int bNn = nb0 + nt * 128;
        float msv[8][2];
#pragma unroll
        for (int j = 0; j < 8; ++j) {
            int c0 = bNn + wn + 8 * j + 2 * tg;
            msv[j][0] = g_msn[c0];
            msv[j][1] = g_msn[c0 + 1];
        }
        float rsum[2][2];
        rsum[0][0] = rsum[0][1] = rsum[1][0] = rsum[1][1] = 0.f;

        __syncthreads();   // all warps' mma reads of the staging buffer are done
#pragma unroll
        for (int half = 0; half < 2; ++half) {
            if (nw == half) {
#pragma unroll
                for (int i = 0; i < 2; ++i) {
                    int srow = wm + 16 * i + g;
#pragma unroll
                    for (int j = 0; j < 8; ++j) {
                        __half h0 = __float2half_rn(__expf(msv[j][0] * (acc[i][j][0] - bsqr[i][0])));
                        __half h1 = __float2half_rn(__expf(msv[j][1] * (acc[i][j][1] - bsqr[i][0])));
                        __half h2 = __float2half_rn(__expf(msv[j][0] * (acc[i][j][2] - bsqr[i][1])));
                        __half h3 = __float2half_rn(__expf(msv[j][1] * (acc[i][j][3] - bsqr[i][1])));
                        int scol = 8 * j + 2 * tg;
                        *(__half2*)(stg + srow * RS + scol * 2)       = __halves2half2(h0, h1);
                        *(__half2*)(stg + (srow + 8) * RS + scol * 2) = __halves2half2(h2, h3);
                        rsum[i][0] += __half2float(h0) + __half2float(h1);
                        rsum[i][1] += __half2float(h2) + __half2float(h3);
                    }
                }
            }
            __syncthreads();
            // coalesced copy-out: 128 rows x 64 halves (128 B data per row)
#pragma unroll
            for (int s = 0; s < 4; ++s) {
                int id = tid + s * 256;
                int row = id >> 3, c = id & 7;
                uint4 v = *(const uint4*)(stg + row * RS + c * 16);
                *(uint4*)&g_SH[(size_t)(bNp + row) * NN + bNn + half * 64 + c * 8] = v;
            }
            __syncthreads();
        }

#pragma unroll
        for (int i = 0; i < 2; ++i)
#pragma unroll
            for (int d = 0; d < 2; ++d) {
                float s = rsum[i][d];
                s += __shfl_xor_sync(0xffffffffu, s, 1);
                s += __shfl_xor_sync(0xffffffffu, s, 2);
                if (tg == 0) red[nw][wm + 16 * i + 8 * d + g] = s;
            }
        __syncthreads();
        if (tid < 128)
            g_part[(size_t)(blockIdx.x * 2 + nt) * NP + bNp + tid] =
                red[0][tid] + red[1][tid];
    };

    auto zacc = [&]() {
#pragma unroll
        for (int i = 0; i < 2; ++i)
#pragma unroll
            for (int j = 0; j < 8; ++j)
#pragma unroll
                for (int r = 0; r < 4; ++r) acc[i][j][r] = 0.f;
    };

    // prologue: G0 = {Q0, Q1, M(n0,k0)->M0}, G1 = {M(n0,k1)->M1}
    load_q(0); load_q(1); load_m(0, 0, 0); CP_COMMIT();
    load_m(0, 1, 1); CP_COMMIT();

    // s0: (n0,k0) reads M0; refill -> M2
    CP_WAIT(1); __syncthreads();
    load_m(1, 0, 2); CP_COMMIT();       // G2
    zacc();
    mma_step(QB0, MB[0]);
    // s1: (n0,k1) reads M1 (last read of M1); refill (n1,k1) -> M0
    CP_WAIT(1); __syncthreads();
    load_m(1, 1, 0); CP_COMMIT();       // G3
    mma_step(QB1, MB[1]);
    epilogue(0);
    // s2: (n1,k0) reads M2
    CP_WAIT(1); __syncthreads();
    zacc();
    mma_step(QB0, MB[2]);
    // s3: (n1,k1) reads M0
    CP_WAIT(0); __syncthreads();
    mma_step(QB1, MB[0]);
    epilogue(1);
}

// ---------------- rinv ----------------
__global__ void rinv_kernel() {
    __shared__ float red[8][33];
    const int lane = threadIdx.x;
    const int bg   = threadIdx.y;
    const int p = blockIdx.x * 32 + lane;
    float s = 0.f;
#pragma unroll
    for (int u = 0; u < 8; ++u)
        s += g_part[(size_t)(bg * 8 + u) * NP + p];
    red[bg][lane] = s;
    __syncthreads();
    if (bg == 0) {
#pragma unroll
        for (int y = 1; y < 8; ++y) s += red[y][lane];
        g_rinv[p] = 1.0f / s;
    }
}

// ---------------- readout GEMM: fp16 m16n8k16 + LDSM, 4 warps x 64x64 tiles ------
// out[v][p] = rinv[p] * sum_n MVh[v][n] * E^T[p][n]
// CTA 128x128, 128 threads (warp grid 2x2), BK=64, 3-stage cp.async ring.
#define OBK   64
#define ONKT  (NN / OBK)        // 128
#define OSTG  (2 * TSZ)         // 36864 B per stage
#define OSMEM (3 * OSTG)        // 110592 B

__global__ __launch_bounds__(128, 2) void out_gemm_kernel(float* __restrict__ out) {
    extern __shared__ __half Sh[];
    const int tid  = threadIdx.x;
    const int warp = tid >> 5;
    const int lane = tid & 31;
    const int bM = blockIdx.x * 128;   // v offset (x fastest -> 8 CTAs share E strip)
    const int bN = blockIdx.y * 128;   // p offset
    const int wm = (warp & 1) * 64;    // v warp tile (64)
    const int wn = (warp >> 1) * 64;   // p warp tile (64)
    const int g  = lane >> 2;
    const int tg = lane & 3;
    const uint32_t sbase = smem_u32(Sh);

    uint32_t aoff[4];
#pragma unroll
    for (int i = 0; i < 4; ++i)
        aoff[i] = (uint32_t)(wm + 16 * i + (lane & 15)) * RS + ((lane >> 4) & 1) * 16;
    uint32_t boff[4];
#pragma unroll
    for (int jp = 0; jp < 4; ++jp)
        boff[jp] = TSZ +
                   (uint32_t)(wn + 16 * jp + ((lane >> 4) & 1) * 8 + (lane & 7)) * RS +
                   ((lane >> 3) & 1) * 16;

    float acc[4][8][4];
#pragma unroll
    for (int i = 0; i < 4; ++i)
#pragma unroll
        for (int j = 0; j < 8; ++j)
#pragma unroll
            for (int r = 0; r < 4; ++r) acc[i][j][r] = 0.f;

    auto load_A_half = [&](int kt, int st, int h) {
        uint32_t ab = sbase + st * OSTG;
#pragma unroll
        for (int s = 0; s < 4; ++s) {
            int id = tid + (h * 4 + s) * 128;
            int r = id >> 3, c = id & 7;
            cp16(ab + r * RS + c * 16, &g_MVh[(size_t)(bM + r) * NN + kt * OBK + c * 8]);
        }
    };
    auto load_B_half = [&](int kt, int st, int h) {
        uint32_t bb = sbase + st * OSTG + TSZ;
#pragma unroll
        for (int s = 0; s < 4; ++s) {
            int id = tid + (h * 4 + s) * 128;
            int r = id >> 3, c = id & 7;
            cp16(bb + r * RS + c * 16, &g_SH[(size_t)(bN + r) * NN + kt * OBK + c * 8]);
        }
    };

    load_A_half(0, 0, 0); load_A_half(0, 0, 1);
    load_B_half(0, 0, 0); load_B_half(0, 0, 1); CP_COMMIT();
    load_A_half(1, 1, 0); load_A_half(1, 1, 1);
    load_B_half(1, 1, 0); load_B_half(1, 1, 1); CP_COMMIT();

    for (int kt = 0; kt < ONKT; ++kt) {
        if (kt + 1 < ONKT) CP_WAIT(1);
        else               CP_WAIT(0);
        __syncthreads();

        const uint32_t stb = sbase + (kt % 3) * OSTG;
        const bool pf = (kt + 2 < ONKT);
        const int pfs = (kt + 2) % 3;

#pragma unroll
        for (int ks = 0; ks < 4; ++ks) {       // 4 x k16
            const uint32_t kb = ks * 32;
            uint32_t af[4][4], bf[4][4];
            ldsm4(af[0], stb + aoff[0] + kb);
            ldsm4(af[1], stb + aoff[1] + kb);
            ldsm4(af[2], stb + aoff[2] + kb);
            ldsm4(af[3], stb + aoff[3] + kb);
            ldsm4(bf[0], stb + boff[0] + kb);
            ldsm4(bf[1], stb + boff[1] + kb);
            MMA_F16U(acc[0][0], af[0], bf[0][0], bf[0][1]);
            MMA_F16U(acc[0][1], af[0], bf[0][2], bf[0][3]);
            MMA_F16U(acc[1][0], af[1], bf[0][0], bf[0][1]);
            MMA_F16U(acc[1][1], af[1], bf[0][2], bf[0][3]);
            ldsm4(bf[2], stb + boff[2] + kb);
            MMA_F16U(acc[2][0], af[2], bf[0][0], bf[0][1]);
            MMA_F16U(acc[2][1], af[2], bf[0][2], bf[0][3]);
            MMA_F16U(acc[3][0], af[3], bf[0][0], bf[0][1]);
            MMA_F16U(acc[3][1], af[3], bf[0][2], bf[0][3]);
            ldsm4(bf[3], stb + boff[3] + kb);
#pragma unroll
            for (int i = 0; i < 4; ++i) {
                MMA_F16U(acc[i][2], af[i], bf[1][0], bf[1][1]);
                MMA_F16U(acc[i][3], af[i], bf[1][2], bf[1][3]);
            }
#pragma unroll
            for (int i = 0; i < 4; ++i)
#pragma unroll
                for (int jp = 2; jp < 4; ++jp) {
                    MMA_F16U(acc[i][2 * jp],     af[i], bf[jp][0], bf[jp][1]);
                    MMA_F16U(acc[i][2 * jp + 1], af[i], bf[jp][2], bf[jp][3]);
                }
            // spread next-stage loads across all 4 ks slots
            if (pf) {
                if (ks == 0)      load_A_half(kt + 2, pfs, 0);
                else if (ks == 1) load_A_half(kt + 2, pfs, 1);
                else if (ks == 2) load_B_half(kt + 2, pfs, 0);
                else            { load_B_half(kt + 2, pfs, 1); CP_COMMIT(); }
            }
        }
    }

    // epilogue: scale by rinv[p]
#pragma unroll
    for (int j = 0; j < 8; ++j) {
        int c = bN + wn + 8 * j + 2 * tg;
        float r0 = g_rinv[c];
        float r1 = g_rinv[c + 1];
#pragma unroll
        for (int i = 0; i < 4; ++i) {
            int rr = bM + wm + 16 * i + g;
            *(float2*)&out[(size_t)rr * NP + c] =
                make_float2(acc[i][j][0] * r0, acc[i][j][1] * r1);
            *(float2*)&out[(size_t)(rr + 8) * NP + c] =
                make_float2(acc[i][j][2] * r0, acc[i][j][3] * r1);
        }
    }
}

// ---------------- launch ----------------
extern "C" void kernel_launch(void* const* d_in, const int* in_sizes, int n_in,
                              void* d_out, int out_size) {
    const float* qk = (const float*)d_in[0];
    const float* qe = (const float*)d_in[1];
    const float* mk = (const float*)d_in[2];
    const float* ms = (const float*)d_in[3];
    const float* mv = (const float*)d_in[4];
    float* out = (float*)d_out;

    cudaFuncSetAttribute(sim_kernel, cudaFuncAttributeMaxDynamicSharedMemorySize, SSMEM);
    cudaFuncSetAttribute(out_gemm_kernel, cudaFuncAttributeMaxDynamicSharedMemorySize, OSMEM);

    prep_q_kernel<<<NP / 32, dim3(32, 8)>>>(qk, qe);
    prep_m_kernel<<<NN / 32, dim3(32, 8)>>>(mk, ms);
    prep_mv_kernel<<<(NV * NN / 4) / 256, 256>>>(mv);
    sim_kernel<<<dim3(NN / 256, NP / 128), 256, SSMEM>>>();
    rinv_kernel<<<NP / 32, dim3(32, 8)>>>();
    out_gemm_kernel<<<dim3(NV / 128, NP / 128), 128, OSMEM>>>(out);
}